// round 7
// baseline (speedup 1.0000x reference)
#include <cuda_runtime.h>
#include <cstdint>
#include <math.h>

#define NNODES   96000
#define NPERTYPE 32000
#define NEDGES   1536000
#define HD       32            // H*D
#define NEG_SLOPE 0.2f
#define BUCKET_CAP 64          // max in-degree capacity (Poisson(16): P(>64) ~ 1e-20)
#define ROWS_PER_BLK 128
#define BLKS_PER_TYPE (NPERTYPE / ROWS_PER_BLK)   // 250
#define XS_STRIDE 33           // smem row stride (odd -> conflict-free col reads)

// ---------------- scratch (static device globals; no allocation) ----------------
__device__ float g_h [(size_t)NNODES * HD];          // [N,32] embedded features
__device__ float g_el[(size_t)NNODES * 4];           // [N,H]
__device__ float g_er[(size_t)NNODES * 4];           // [N,H]
__device__ int   g_count[NNODES];                    // in-degree (atomic cursor)
__device__ int   g_bucket[(size_t)NNODES * BUCKET_CAP]; // src ids grouped by dst

// ---------------- kernel 1: register-blocked per-type embed + attention projections ----
// Block: 256 threads = 8 warps, 128 rows. Warp w: rows 16w..16w+15.
// Thread: rgrp=lane>>2 (2 rows: 2*rgrp..+1), cgrp=lane&3 (8 cols == head cgrp).
// K chunked by 32, staged into smem xs[128][33].
template<int K>
__device__ __forceinline__ void embed_tile(
    float* __restrict__ xs,
    const float* __restrict__ x,            // type-local [NPERTYPE, K]
    const float* __restrict__ W,            // [K, 32]
    const float* __restrict__ b,            // [32]
    const float* __restrict__ attn_l, const float* __restrict__ attn_r,
    int type_row_base, int grow_base)
{
    const int t = threadIdx.x;
    const int warp = t >> 5, lane = t & 31;
    const int rgrp = lane >> 2, cgrp = lane & 3;
    const int Rloc = warp * 16 + rgrp * 2;   // local row base (2 rows)

    float4 bv0 = __ldg((const float4*)b + cgrp * 2);
    float4 bv1 = __ldg((const float4*)b + cgrp * 2 + 1);
    float acc[2][8];
    #pragma unroll
    for (int i = 0; i < 2; i++) {
        acc[i][0] = bv0.x; acc[i][1] = bv0.y; acc[i][2] = bv0.z; acc[i][3] = bv0.w;
        acc[i][4] = bv1.x; acc[i][5] = bv1.y; acc[i][6] = bv1.z; acc[i][7] = bv1.w;
    }

    #pragma unroll
    for (int k0 = 0; k0 < K; k0 += 32) {
        __syncthreads();
        // stage 128 rows x 32 k-cols, coalesced; banks (row+c)%32 conflict-free
        #pragma unroll
        for (int idx = t; idx < ROWS_PER_BLK * 32; idx += 256) {
            int row = idx >> 5, c = idx & 31;
            xs[row * XS_STRIDE + c] = __ldg(&x[(size_t)(type_row_base + row) * K + k0 + c]);
        }
        __syncthreads();

        #pragma unroll 8
        for (int kk = 0; kk < 32; kk++) {
            float4 w0 = __ldg((const float4*)(W + (size_t)(k0 + kk) * HD) + cgrp * 2);
            float4 w1 = __ldg((const float4*)(W + (size_t)(k0 + kk) * HD) + cgrp * 2 + 1);
            #pragma unroll
            for (int i = 0; i < 2; i++) {
                float xv = xs[(Rloc + i) * XS_STRIDE + kk];
                acc[i][0] = fmaf(xv, w0.x, acc[i][0]);
                acc[i][1] = fmaf(xv, w0.y, acc[i][1]);
                acc[i][2] = fmaf(xv, w0.z, acc[i][2]);
                acc[i][3] = fmaf(xv, w0.w, acc[i][3]);
                acc[i][4] = fmaf(xv, w1.x, acc[i][4]);
                acc[i][5] = fmaf(xv, w1.y, acc[i][5]);
                acc[i][6] = fmaf(xv, w1.z, acc[i][6]);
                acc[i][7] = fmaf(xv, w1.w, acc[i][7]);
            }
        }
    }

    // epilogue: h store + thread-local el/er (this thread's 8 cols == head cgrp)
    float4 al0 = __ldg((const float4*)attn_l + cgrp * 2);
    float4 al1 = __ldg((const float4*)attn_l + cgrp * 2 + 1);
    float4 ar0 = __ldg((const float4*)attn_r + cgrp * 2);
    float4 ar1 = __ldg((const float4*)attn_r + cgrp * 2 + 1);
    #pragma unroll
    for (int i = 0; i < 2; i++) {
        int grow = grow_base + Rloc + i;
        float4 v0 = make_float4(acc[i][0], acc[i][1], acc[i][2], acc[i][3]);
        float4 v1 = make_float4(acc[i][4], acc[i][5], acc[i][6], acc[i][7]);
        *(float4*)&g_h[(size_t)grow * HD + cgrp * 8]     = v0;
        *(float4*)&g_h[(size_t)grow * HD + cgrp * 8 + 4] = v1;
        float el = v0.x * al0.x + v0.y * al0.y + v0.z * al0.z + v0.w * al0.w
                 + v1.x * al1.x + v1.y * al1.y + v1.z * al1.z + v1.w * al1.w;
        float er = v0.x * ar0.x + v0.y * ar0.y + v0.z * ar0.z + v0.w * ar0.w
                 + v1.x * ar1.x + v1.y * ar1.y + v1.z * ar1.z + v1.w * ar1.w;
        g_el[grow * 4 + cgrp] = el;
        g_er[grow * 4 + cgrp] = er;
    }
}

__global__ void __launch_bounds__(256, 4) embed_kernel(
    const float* __restrict__ x0, const float* __restrict__ x1, const float* __restrict__ x2,
    const float* __restrict__ W0, const float* __restrict__ b0,
    const float* __restrict__ W1, const float* __restrict__ b1,
    const float* __restrict__ W2, const float* __restrict__ b2,
    const float* __restrict__ attn_l, const float* __restrict__ attn_r)
{
    __shared__ float xs[ROWS_PER_BLK * XS_STRIDE];

    // fused zeroing of in-degree counters (750*256 = 192000 >= NNODES)
    int tid = blockIdx.x * blockDim.x + threadIdx.x;
    if (tid < NNODES) g_count[tid] = 0;

    int type = blockIdx.x % 3;              // interleave types for load balance
    int tb   = blockIdx.x / 3;
    int type_row_base = tb * ROWS_PER_BLK;
    int grow_base = type * NPERTYPE + type_row_base;

    if (type == 0)      embed_tile<128>(xs, x0, W0, b0, attn_l, attn_r, type_row_base, grow_base);
    else if (type == 1) embed_tile<64> (xs, x1, W1, b1, attn_l, attn_r, type_row_base, grow_base);
    else                embed_tile<32> (xs, x2, W2, b2, attn_l, attn_r, type_row_base, grow_base);
}

// ---------------- kernel 2: scatter edges into fixed-capacity buckets ----------------
__global__ void scatter_kernel(const int* __restrict__ src, const int* __restrict__ dst) {
    int i4 = blockIdx.x * blockDim.x + threadIdx.x;
    if (i4 * 4 >= NEDGES) return;
    int4 s = __ldg((const int4*)src + i4);
    int4 d = __ldg((const int4*)dst + i4);
    int p;
    p = atomicAdd(&g_count[d.x], 1); if (p < BUCKET_CAP) g_bucket[(size_t)d.x * BUCKET_CAP + p] = s.x;
    p = atomicAdd(&g_count[d.y], 1); if (p < BUCKET_CAP) g_bucket[(size_t)d.y * BUCKET_CAP + p] = s.y;
    p = atomicAdd(&g_count[d.z], 1); if (p < BUCKET_CAP) g_bucket[(size_t)d.z * BUCKET_CAP + p] = s.z;
    p = atomicAdd(&g_count[d.w], 1); if (p < BUCKET_CAP) g_bucket[(size_t)d.w * BUCKET_CAP + p] = s.w;
}

// ---------------- kernel 3: warp-per-dst softmax aggregation + ELU ----------------
// exp without max-subtraction (|e| small, softmax shift-invariant); 4-wide pipeline.
__global__ void agg_kernel(float* __restrict__ out) {
    int gw   = (blockIdx.x * blockDim.x + threadIdx.x) >> 5;
    int lane = threadIdx.x & 31;
    if (gw >= NNODES) return;

    int deg = g_count[gw];
    deg = (deg > BUCKET_CAP) ? BUCKET_CAP : deg;
    const int hh = lane >> 3;
    const float er_h = g_er[gw * 4 + hh];
    const int* __restrict__ bkt = g_bucket + (size_t)gw * BUCKET_CAP;

    float s0 = 0.f, s1 = 0.f, s2 = 0.f, s3 = 0.f;
    float a0 = 0.f, a1 = 0.f, a2 = 0.f, a3 = 0.f;
    int t = 0;
    for (; t + 3 < deg; t += 4) {
        int4 ii = __ldg((const int4*)(bkt + t));          // 16B-aligned (t multiple of 4)
        float e0 = __ldg(&g_el[ii.x * 4 + hh]) + er_h;
        float e1 = __ldg(&g_el[ii.y * 4 + hh]) + er_h;
        float e2 = __ldg(&g_el[ii.z * 4 + hh]) + er_h;
        float e3 = __ldg(&g_el[ii.w * 4 + hh]) + er_h;
        float h0 = __ldg(&g_h[(size_t)ii.x * HD + lane]);
        float h1 = __ldg(&g_h[(size_t)ii.y * HD + lane]);
        float h2 = __ldg(&g_h[(size_t)ii.z * HD + lane]);
        float h3 = __ldg(&g_h[(size_t)ii.w * HD + lane]);
        e0 = (e0 > 0.f) ? e0 : NEG_SLOPE * e0;
        e1 = (e1 > 0.f) ? e1 : NEG_SLOPE * e1;
        e2 = (e2 > 0.f) ? e2 : NEG_SLOPE * e2;
        e3 = (e3 > 0.f) ? e3 : NEG_SLOPE * e3;
        float x0 = __expf(e0), x1 = __expf(e1), x2 = __expf(e2), x3 = __expf(e3);
        s0 += x0;              s1 += x1;              s2 += x2;              s3 += x3;
        a0 = fmaf(x0, h0, a0); a1 = fmaf(x1, h1, a1); a2 = fmaf(x2, h2, a2); a3 = fmaf(x3, h3, a3);
    }
    for (; t < deg; t++) {
        int i0 = __ldg(bkt + t);
        float e0 = __ldg(&g_el[i0 * 4 + hh]) + er_h;
        float h0 = __ldg(&g_h[(size_t)i0 * HD + lane]);
        e0 = (e0 > 0.f) ? e0 : NEG_SLOPE * e0;
        float x0 = __expf(e0);
        s0 += x0;
        a0 = fmaf(x0, h0, a0);
    }
    float s = (s0 + s1) + (s2 + s3);
    float acc = (a0 + a1) + (a2 + a3);
    float v = acc / (s + 1e-9f);
    v = (v > 0.f) ? v : expm1f(v);    // ELU
    out[(size_t)gw * HD + lane] = v;
}

// ---------------- launch ----------------
extern "C" void kernel_launch(void* const* d_in, const int* in_sizes, int n_in,
                              void* d_out, int out_size)
{
    const float* x0 = (const float*)d_in[0];
    const float* x1 = (const float*)d_in[1];
    const float* x2 = (const float*)d_in[2];
    const float* W0 = (const float*)d_in[3];
    const float* b0 = (const float*)d_in[4];
    const float* W1 = (const float*)d_in[5];
    const float* b1 = (const float*)d_in[6];
    const float* W2 = (const float*)d_in[7];
    const float* b2 = (const float*)d_in[8];
    const float* attn_l = (const float*)d_in[9];
    const float* attn_r = (const float*)d_in[10];

    const int* src; const int* dst;
    if (n_in >= 17 && in_sizes[11] == NNODES) {  // setup_inputs dict order: type_mask at 11
        src = (const int*)d_in[15];
        dst = (const int*)d_in[16];
    } else {                                     // reference arg order: idx0..idx2 at 11..13
        src = (const int*)d_in[14];
        dst = (const int*)d_in[15];
    }
    float* out = (float*)d_out;

    const int TB = 256;
    embed_kernel<<<3 * BLKS_PER_TYPE, TB>>>(x0, x1, x2, W0, b0, W1, b1, W2, b2,
                                            attn_l, attn_r);
    scatter_kernel<<<(NEDGES / 4 + TB - 1) / TB, TB>>>(src, dst);
    agg_kernel<<<(NNODES * 32 + TB - 1) / TB, TB>>>(out);
}

// round 9
// speedup vs baseline: 1.0859x; 1.0859x over previous
#include <cuda_runtime.h>
#include <cstdint>
#include <math.h>

#define NNODES   96000
#define NPERTYPE 32000
#define NEDGES   1536000
#define HD       32            // H*D
#define NEG_SLOPE 0.2f
#define BUCKET_CAP 64          // max in-degree capacity (Poisson(16): P(>64) ~ 1e-20)
#define ROWS_PER_BLK 128
#define BLKS_PER_TYPE (NPERTYPE / ROWS_PER_BLK)   // 250
#define XS_STRIDE 36           // 16B-aligned float4 stores; reads conflict-free

// ---------------- scratch (static device globals; no allocation) ----------------
__device__ float g_h [(size_t)NNODES * HD];          // [N,32] embedded features
__device__ float g_el[(size_t)NNODES * 4];           // [N,H]
__device__ float g_er[(size_t)NNODES * 4];           // [N,H]
__device__ int   g_count[NNODES];                    // in-degree (atomic cursor)
__device__ int   g_bucket[(size_t)NNODES * BUCKET_CAP]; // src ids grouped by dst

// ---------------- cp.async helpers ----------------
__device__ __forceinline__ void cp_async16(void* smem_ptr, const void* gptr) {
    uint32_t sa = (uint32_t)__cvta_generic_to_shared(smem_ptr);
    asm volatile("cp.async.cg.shared.global [%0], [%1], 16;" :: "r"(sa), "l"(gptr));
}
__device__ __forceinline__ void cp_commit() {
    asm volatile("cp.async.commit_group;");
}
__device__ __forceinline__ void cp_wait1() {
    asm volatile("cp.async.wait_group 1;");
}
__device__ __forceinline__ void cp_wait0() {
    asm volatile("cp.async.wait_group 0;");
}

// ---------------- kernel 1: double-buffered cp.async embed + attention projections ----
// Block: 256 threads = 8 warps, 128 rows. Warp w: rows [16w, 16w+16).
// Thread: rgrp=lane>>2 (rows 16w+rgrp, 16w+rgrp+8), cgrp=lane&3 (8 cols == head cgrp).
// K chunked by 32; chunk staged via cp.async (4x 16B per thread) into xs[buf][128][36].
template<int K>
__device__ __forceinline__ void embed_tile(
    float (* __restrict__ xs)[ROWS_PER_BLK * XS_STRIDE],
    const float* __restrict__ x,            // type-local [NPERTYPE, K]
    const float* __restrict__ W,            // [K, 32]
    const float* __restrict__ b,            // [32]
    const float* __restrict__ attn_l, const float* __restrict__ attn_r,
    int type_row_base, int grow_base)
{
    constexpr int NC = K / 32;              // chunks
    const int t = threadIdx.x;
    const int warp = t >> 5, lane = t & 31;
    const int rgrp = lane >> 2, cgrp = lane & 3;
    const int R0 = warp * 16 + rgrp;        // rows R0 and R0+8

    // staging coords for this thread: 4 float4s per chunk
    auto stage = [&](int buf, int k0) {
        #pragma unroll
        for (int q = 0; q < 4; q++) {
            int idx = t + 256 * q;
            int row = idx >> 3, c4 = (idx & 7) * 4;
            cp_async16(&xs[buf][row * XS_STRIDE + c4],
                       &x[(size_t)(type_row_base + row) * K + k0 + c4]);
        }
        cp_commit();
    };

    float4 bv0 = __ldg((const float4*)b + cgrp * 2);
    float4 bv1 = __ldg((const float4*)b + cgrp * 2 + 1);
    float acc[2][8];
    #pragma unroll
    for (int i = 0; i < 2; i++) {
        acc[i][0] = bv0.x; acc[i][1] = bv0.y; acc[i][2] = bv0.z; acc[i][3] = bv0.w;
        acc[i][4] = bv1.x; acc[i][5] = bv1.y; acc[i][6] = bv1.z; acc[i][7] = bv1.w;
    }

    stage(0, 0);

    #pragma unroll
    for (int c = 0; c < NC; c++) {
        if (c + 1 < NC) stage((c + 1) & 1, (c + 1) * 32);   // buffer last read in chunk c-1 (synced)
        if (c + 1 < NC) cp_wait1(); else cp_wait0();        // chunk c data arrived
        __syncthreads();

        const float* xb = xs[c & 1];
        #pragma unroll 8
        for (int kk = 0; kk < 32; kk++) {
            float4 w0 = __ldg((const float4*)(W + (size_t)(c * 32 + kk) * HD) + cgrp * 2);
            float4 w1 = __ldg((const float4*)(W + (size_t)(c * 32 + kk) * HD) + cgrp * 2 + 1);
            #pragma unroll
            for (int i = 0; i < 2; i++) {
                float xv = xb[(R0 + i * 8) * XS_STRIDE + kk];
                acc[i][0] = fmaf(xv, w0.x, acc[i][0]);
                acc[i][1] = fmaf(xv, w0.y, acc[i][1]);
                acc[i][2] = fmaf(xv, w0.z, acc[i][2]);
                acc[i][3] = fmaf(xv, w0.w, acc[i][3]);
                acc[i][4] = fmaf(xv, w1.x, acc[i][4]);
                acc[i][5] = fmaf(xv, w1.y, acc[i][5]);
                acc[i][6] = fmaf(xv, w1.z, acc[i][6]);
                acc[i][7] = fmaf(xv, w1.w, acc[i][7]);
            }
        }
        __syncthreads();
    }

    // epilogue: h store + thread-local el/er (this thread's 8 cols == head cgrp)
    float4 al0 = __ldg((const float4*)attn_l + cgrp * 2);
    float4 al1 = __ldg((const float4*)attn_l + cgrp * 2 + 1);
    float4 ar0 = __ldg((const float4*)attn_r + cgrp * 2);
    float4 ar1 = __ldg((const float4*)attn_r + cgrp * 2 + 1);
    #pragma unroll
    for (int i = 0; i < 2; i++) {
        int grow = grow_base + R0 + i * 8;
        float4 v0 = make_float4(acc[i][0], acc[i][1], acc[i][2], acc[i][3]);
        float4 v1 = make_float4(acc[i][4], acc[i][5], acc[i][6], acc[i][7]);
        *(float4*)&g_h[(size_t)grow * HD + cgrp * 8]     = v0;
        *(float4*)&g_h[(size_t)grow * HD + cgrp * 8 + 4] = v1;
        float el = v0.x * al0.x + v0.y * al0.y + v0.z * al0.z + v0.w * al0.w
                 + v1.x * al1.x + v1.y * al1.y + v1.z * al1.z + v1.w * al1.w;
        float er = v0.x * ar0.x + v0.y * ar0.y + v0.z * ar0.z + v0.w * ar0.w
                 + v1.x * ar1.x + v1.y * ar1.y + v1.z * ar1.z + v1.w * ar1.w;
        g_el[grow * 4 + cgrp] = el;
        g_er[grow * 4 + cgrp] = er;
    }
}

__global__ void __launch_bounds__(256, 4) embed_kernel(
    const float* __restrict__ x0, const float* __restrict__ x1, const float* __restrict__ x2,
    const float* __restrict__ W0, const float* __restrict__ b0,
    const float* __restrict__ W1, const float* __restrict__ b1,
    const float* __restrict__ W2, const float* __restrict__ b2,
    const float* __restrict__ attn_l, const float* __restrict__ attn_r)
{
    __shared__ float xs[2][ROWS_PER_BLK * XS_STRIDE];

    // fused zeroing of in-degree counters (750*256 = 192000 >= NNODES)
    int tid = blockIdx.x * blockDim.x + threadIdx.x;
    if (tid < NNODES) g_count[tid] = 0;

    int type = blockIdx.x % 3;              // interleave types for load balance
    int tb   = blockIdx.x / 3;
    int type_row_base = tb * ROWS_PER_BLK;
    int grow_base = type * NPERTYPE + type_row_base;

    if (type == 0)      embed_tile<128>(xs, x0, W0, b0, attn_l, attn_r, type_row_base, grow_base);
    else if (type == 1) embed_tile<64> (xs, x1, W1, b1, attn_l, attn_r, type_row_base, grow_base);
    else                embed_tile<32> (xs, x2, W2, b2, attn_l, attn_r, type_row_base, grow_base);
}

// ---------------- kernel 2: scatter edges into fixed-capacity buckets ----------------
__global__ void scatter_kernel(const int* __restrict__ src, const int* __restrict__ dst) {
    int i4 = blockIdx.x * blockDim.x + threadIdx.x;
    if (i4 * 4 >= NEDGES) return;
    int4 s = __ldg((const int4*)src + i4);
    int4 d = __ldg((const int4*)dst + i4);
    int p;
    p = atomicAdd(&g_count[d.x], 1); if (p < BUCKET_CAP) g_bucket[(size_t)d.x * BUCKET_CAP + p] = s.x;
    p = atomicAdd(&g_count[d.y], 1); if (p < BUCKET_CAP) g_bucket[(size_t)d.y * BUCKET_CAP + p] = s.y;
    p = atomicAdd(&g_count[d.z], 1); if (p < BUCKET_CAP) g_bucket[(size_t)d.z * BUCKET_CAP + p] = s.z;
    p = atomicAdd(&g_count[d.w], 1); if (p < BUCKET_CAP) g_bucket[(size_t)d.w * BUCKET_CAP + p] = s.w;
}

// ---------------- kernel 3: warp-per-dst softmax aggregation + ELU ----------------
// exp without max-subtraction (|e| small, softmax shift-invariant); 4-wide pipeline.
__global__ void agg_kernel(float* __restrict__ out) {
    int gw   = (blockIdx.x * blockDim.x + threadIdx.x) >> 5;
    int lane = threadIdx.x & 31;
    if (gw >= NNODES) return;

    int deg = g_count[gw];
    deg = (deg > BUCKET_CAP) ? BUCKET_CAP : deg;
    const int hh = lane >> 3;
    const float er_h = g_er[gw * 4 + hh];
    const int* __restrict__ bkt = g_bucket + (size_t)gw * BUCKET_CAP;

    float s0 = 0.f, s1 = 0.f, s2 = 0.f, s3 = 0.f;
    float a0 = 0.f, a1 = 0.f, a2 = 0.f, a3 = 0.f;
    int t = 0;
    for (; t + 3 < deg; t += 4) {
        int4 ii = __ldg((const int4*)(bkt + t));          // 16B-aligned (t multiple of 4)
        float e0 = __ldg(&g_el[ii.x * 4 + hh]) + er_h;
        float e1 = __ldg(&g_el[ii.y * 4 + hh]) + er_h;
        float e2 = __ldg(&g_el[ii.z * 4 + hh]) + er_h;
        float e3 = __ldg(&g_el[ii.w * 4 + hh]) + er_h;
        float h0 = __ldg(&g_h[(size_t)ii.x * HD + lane]);
        float h1 = __ldg(&g_h[(size_t)ii.y * HD + lane]);
        float h2 = __ldg(&g_h[(size_t)ii.z * HD + lane]);
        float h3 = __ldg(&g_h[(size_t)ii.w * HD + lane]);
        e0 = (e0 > 0.f) ? e0 : NEG_SLOPE * e0;
        e1 = (e1 > 0.f) ? e1 : NEG_SLOPE * e1;
        e2 = (e2 > 0.f) ? e2 : NEG_SLOPE * e2;
        e3 = (e3 > 0.f) ? e3 : NEG_SLOPE * e3;
        float x0 = __expf(e0), x1 = __expf(e1), x2 = __expf(e2), x3 = __expf(e3);
        s0 += x0;              s1 += x1;              s2 += x2;              s3 += x3;
        a0 = fmaf(x0, h0, a0); a1 = fmaf(x1, h1, a1); a2 = fmaf(x2, h2, a2); a3 = fmaf(x3, h3, a3);
    }
    for (; t < deg; t++) {
        int i0 = __ldg(bkt + t);
        float e0 = __ldg(&g_el[i0 * 4 + hh]) + er_h;
        float h0 = __ldg(&g_h[(size_t)i0 * HD + lane]);
        e0 = (e0 > 0.f) ? e0 : NEG_SLOPE * e0;
        float x0 = __expf(e0);
        s0 += x0;
        a0 = fmaf(x0, h0, a0);
    }
    float s = (s0 + s1) + (s2 + s3);
    float acc = (a0 + a1) + (a2 + a3);
    float v = acc / (s + 1e-9f);
    v = (v > 0.f) ? v : expm1f(v);    // ELU
    out[(size_t)gw * HD + lane] = v;
}

// ---------------- launch ----------------
extern "C" void kernel_launch(void* const* d_in, const int* in_sizes, int n_in,
                              void* d_out, int out_size)
{
    const float* x0 = (const float*)d_in[0];
    const float* x1 = (const float*)d_in[1];
    const float* x2 = (const float*)d_in[2];
    const float* W0 = (const float*)d_in[3];
    const float* b0 = (const float*)d_in[4];
    const float* W1 = (const float*)d_in[5];
    const float* b1 = (const float*)d_in[6];
    const float* W2 = (const float*)d_in[7];
    const float* b2 = (const float*)d_in[8];
    const float* attn_l = (const float*)d_in[9];
    const float* attn_r = (const float*)d_in[10];

    const int* src; const int* dst;
    if (n_in >= 17 && in_sizes[11] == NNODES) {  // setup_inputs dict order: type_mask at 11
        src = (const int*)d_in[15];
        dst = (const int*)d_in[16];
    } else {                                     // reference arg order: idx0..idx2 at 11..13
        src = (const int*)d_in[14];
        dst = (const int*)d_in[15];
    }
    float* out = (float*)d_out;

    const int TB = 256;
    embed_kernel<<<3 * BLKS_PER_TYPE, TB>>>(x0, x1, x2, W0, b0, W1, b1, W2, b2,
                                            attn_l, attn_r);
    scatter_kernel<<<(NEDGES / 4 + TB - 1) / TB, TB>>>(src, dst);
    agg_kernel<<<(NNODES * 32 + TB - 1) / TB, TB>>>(out);
}

// round 10
// speedup vs baseline: 1.0916x; 1.0053x over previous
#include <cuda_runtime.h>
#include <cstdint>
#include <math.h>

#define NNODES   96000
#define NPERTYPE 32000
#define NEDGES   1536000
#define HD       32            // H*D
#define NEG_SLOPE 0.2f
#define BUCKET_CAP 64          // max in-degree capacity (Poisson(16): P(>64) ~ 1e-20)
#define ROWS_PER_BLK 128
#define BLKS_PER_TYPE (NPERTYPE / ROWS_PER_BLK)   // 250
#define XS_STRIDE 36           // 16B-aligned float4 stores; reads conflict-free

// ---------------- scratch (static device globals; no allocation) ----------------
__device__ float g_h [(size_t)NNODES * HD];          // [N,32] embedded features
__device__ float g_el[(size_t)NNODES * 4];           // [N,H]
__device__ float g_er[(size_t)NNODES * 4];           // [N,H]
__device__ int   g_count[NNODES];                    // in-degree (atomic cursor)
__device__ int   g_bucket[(size_t)NNODES * BUCKET_CAP]; // src ids grouped by dst

// ---------------- cp.async helpers ----------------
__device__ __forceinline__ void cp_async16(void* smem_ptr, const void* gptr) {
    uint32_t sa = (uint32_t)__cvta_generic_to_shared(smem_ptr);
    asm volatile("cp.async.cg.shared.global [%0], [%1], 16;" :: "r"(sa), "l"(gptr));
}
__device__ __forceinline__ void cp_commit() {
    asm volatile("cp.async.commit_group;");
}
__device__ __forceinline__ void cp_wait1() {
    asm volatile("cp.async.wait_group 1;");
}
__device__ __forceinline__ void cp_wait0() {
    asm volatile("cp.async.wait_group 0;");
}

// ---------------- kernel 1: warp-local double-buffered cp.async embed ----------------
// Block: 256 threads = 8 warps, 128 rows. Warp w OWNS rows [16w, 16w+16) exclusively:
// it stages them (cp.async, 4x16B per lane) and computes on them. No block barriers
// in the mainloop — only cp.async.wait_group + __syncwarp, so warps slip freely.
// Thread: rgrp=lane>>2 (rows 16w+rgrp, 16w+rgrp+8), cgrp=lane&3 (8 cols == head cgrp).
template<int K>
__device__ __forceinline__ void embed_tile(
    float (* __restrict__ xs)[ROWS_PER_BLK * XS_STRIDE],
    const float* __restrict__ x,            // type-local [NPERTYPE, K]
    const float* __restrict__ W,            // [K, 32]
    const float* __restrict__ b,            // [32]
    const float* __restrict__ attn_l, const float* __restrict__ attn_r,
    int type_row_base, int grow_base)
{
    constexpr int NC = K / 32;              // chunks
    const int t = threadIdx.x;
    const int warp = t >> 5, lane = t & 31;
    const int rgrp = lane >> 2, cgrp = lane & 3;
    const int R0 = warp * 16 + rgrp;        // rows R0 and R0+8

    // warp-local staging: lane stages 4 float4s of this warp's 16-row slab
    auto stage = [&](int buf, int k0) {
        #pragma unroll
        for (int q = 0; q < 4; q++) {
            int li = lane + 32 * q;                       // 0..127
            int row = warp * 16 + (li >> 3);              // warp-local rows only
            int c4 = (li & 7) * 4;
            cp_async16(&xs[buf][row * XS_STRIDE + c4],
                       &x[(size_t)(type_row_base + row) * K + k0 + c4]);
        }
        cp_commit();
    };

    float4 bv0 = __ldg((const float4*)b + cgrp * 2);
    float4 bv1 = __ldg((const float4*)b + cgrp * 2 + 1);
    float acc[2][8];
    #pragma unroll
    for (int i = 0; i < 2; i++) {
        acc[i][0] = bv0.x; acc[i][1] = bv0.y; acc[i][2] = bv0.z; acc[i][3] = bv0.w;
        acc[i][4] = bv1.x; acc[i][5] = bv1.y; acc[i][6] = bv1.z; acc[i][7] = bv1.w;
    }

    stage(0, 0);

    #pragma unroll
    for (int c = 0; c < NC; c++) {
        if (c + 1 < NC) stage((c + 1) & 1, (c + 1) * 32);   // this warp's slab: last read chunk c-1
        if (c + 1 < NC) cp_wait1(); else cp_wait0();        // chunk c copies (all lanes') issued+landed
        __syncwarp();                                       // cross-lane visibility within warp

        const float* xb = xs[c & 1];
        #pragma unroll 8
        for (int kk = 0; kk < 32; kk++) {
            float4 w0 = __ldg((const float4*)(W + (size_t)(c * 32 + kk) * HD) + cgrp * 2);
            float4 w1 = __ldg((const float4*)(W + (size_t)(c * 32 + kk) * HD) + cgrp * 2 + 1);
            #pragma unroll
            for (int i = 0; i < 2; i++) {
                float xv = xb[(R0 + i * 8) * XS_STRIDE + kk];
                acc[i][0] = fmaf(xv, w0.x, acc[i][0]);
                acc[i][1] = fmaf(xv, w0.y, acc[i][1]);
                acc[i][2] = fmaf(xv, w0.z, acc[i][2]);
                acc[i][3] = fmaf(xv, w0.w, acc[i][3]);
                acc[i][4] = fmaf(xv, w1.x, acc[i][4]);
                acc[i][5] = fmaf(xv, w1.y, acc[i][5]);
                acc[i][6] = fmaf(xv, w1.z, acc[i][6]);
                acc[i][7] = fmaf(xv, w1.w, acc[i][7]);
            }
        }
        __syncwarp();                                       // all lanes done reading before re-stage
    }

    // epilogue: h store + thread-local el/er (this thread's 8 cols == head cgrp)
    float4 al0 = __ldg((const float4*)attn_l + cgrp * 2);
    float4 al1 = __ldg((const float4*)attn_l + cgrp * 2 + 1);
    float4 ar0 = __ldg((const float4*)attn_r + cgrp * 2);
    float4 ar1 = __ldg((const float4*)attn_r + cgrp * 2 + 1);
    #pragma unroll
    for (int i = 0; i < 2; i++) {
        int grow = grow_base + R0 + i * 8;
        float4 v0 = make_float4(acc[i][0], acc[i][1], acc[i][2], acc[i][3]);
        float4 v1 = make_float4(acc[i][4], acc[i][5], acc[i][6], acc[i][7]);
        *(float4*)&g_h[(size_t)grow * HD + cgrp * 8]     = v0;
        *(float4*)&g_h[(size_t)grow * HD + cgrp * 8 + 4] = v1;
        float el = v0.x * al0.x + v0.y * al0.y + v0.z * al0.z + v0.w * al0.w
                 + v1.x * al1.x + v1.y * al1.y + v1.z * al1.z + v1.w * al1.w;
        float er = v0.x * ar0.x + v0.y * ar0.y + v0.z * ar0.z + v0.w * ar0.w
                 + v1.x * ar1.x + v1.y * ar1.y + v1.z * ar1.z + v1.w * ar1.w;
        g_el[grow * 4 + cgrp] = el;
        g_er[grow * 4 + cgrp] = er;
    }
}

__global__ void __launch_bounds__(256) embed_kernel(
    const float* __restrict__ x0, const float* __restrict__ x1, const float* __restrict__ x2,
    const float* __restrict__ W0, const float* __restrict__ b0,
    const float* __restrict__ W1, const float* __restrict__ b1,
    const float* __restrict__ W2, const float* __restrict__ b2,
    const float* __restrict__ attn_l, const float* __restrict__ attn_r)
{
    __shared__ float xs[2][ROWS_PER_BLK * XS_STRIDE];

    // fused zeroing of in-degree counters (750*256 = 192000 >= NNODES)
    int tid = blockIdx.x * blockDim.x + threadIdx.x;
    if (tid < NNODES) g_count[tid] = 0;

    int type = blockIdx.x % 3;              // interleave types for load balance
    int tb   = blockIdx.x / 3;
    int type_row_base = tb * ROWS_PER_BLK;
    int grow_base = type * NPERTYPE + type_row_base;

    if (type == 0)      embed_tile<128>(xs, x0, W0, b0, attn_l, attn_r, type_row_base, grow_base);
    else if (type == 1) embed_tile<64> (xs, x1, W1, b1, attn_l, attn_r, type_row_base, grow_base);
    else                embed_tile<32> (xs, x2, W2, b2, attn_l, attn_r, type_row_base, grow_base);
}

// ---------------- kernel 2: scatter edges into fixed-capacity buckets ----------------
__global__ void scatter_kernel(const int* __restrict__ src, const int* __restrict__ dst) {
    int i4 = blockIdx.x * blockDim.x + threadIdx.x;
    if (i4 * 4 >= NEDGES) return;
    int4 s = __ldg((const int4*)src + i4);
    int4 d = __ldg((const int4*)dst + i4);
    int p;
    p = atomicAdd(&g_count[d.x], 1); if (p < BUCKET_CAP) g_bucket[(size_t)d.x * BUCKET_CAP + p] = s.x;
    p = atomicAdd(&g_count[d.y], 1); if (p < BUCKET_CAP) g_bucket[(size_t)d.y * BUCKET_CAP + p] = s.y;
    p = atomicAdd(&g_count[d.z], 1); if (p < BUCKET_CAP) g_bucket[(size_t)d.z * BUCKET_CAP + p] = s.z;
    p = atomicAdd(&g_count[d.w], 1); if (p < BUCKET_CAP) g_bucket[(size_t)d.w * BUCKET_CAP + p] = s.w;
}

// ---------------- kernel 3: warp-per-dst softmax aggregation + ELU ----------------
// exp without max-subtraction (|e| small, softmax shift-invariant); 4-wide pipeline.
__global__ void agg_kernel(float* __restrict__ out) {
    int gw   = (blockIdx.x * blockDim.x + threadIdx.x) >> 5;
    int lane = threadIdx.x & 31;
    if (gw >= NNODES) return;

    int deg = g_count[gw];
    deg = (deg > BUCKET_CAP) ? BUCKET_CAP : deg;
    const int hh = lane >> 3;
    const float er_h = g_er[gw * 4 + hh];
    const int* __restrict__ bkt = g_bucket + (size_t)gw * BUCKET_CAP;

    float s0 = 0.f, s1 = 0.f, s2 = 0.f, s3 = 0.f;
    float a0 = 0.f, a1 = 0.f, a2 = 0.f, a3 = 0.f;
    int t = 0;
    for (; t + 3 < deg; t += 4) {
        int4 ii = __ldg((const int4*)(bkt + t));          // 16B-aligned (t multiple of 4)
        float e0 = __ldg(&g_el[ii.x * 4 + hh]) + er_h;
        float e1 = __ldg(&g_el[ii.y * 4 + hh]) + er_h;
        float e2 = __ldg(&g_el[ii.z * 4 + hh]) + er_h;
        float e3 = __ldg(&g_el[ii.w * 4 + hh]) + er_h;
        float h0 = __ldg(&g_h[(size_t)ii.x * HD + lane]);
        float h1 = __ldg(&g_h[(size_t)ii.y * HD + lane]);
        float h2 = __ldg(&g_h[(size_t)ii.z * HD + lane]);
        float h3 = __ldg(&g_h[(size_t)ii.w * HD + lane]);
        e0 = (e0 > 0.f) ? e0 : NEG_SLOPE * e0;
        e1 = (e1 > 0.f) ? e1 : NEG_SLOPE * e1;
        e2 = (e2 > 0.f) ? e2 : NEG_SLOPE * e2;
        e3 = (e3 > 0.f) ? e3 : NEG_SLOPE * e3;
        float x0 = __expf(e0), x1 = __expf(e1), x2 = __expf(e2), x3 = __expf(e3);
        s0 += x0;              s1 += x1;              s2 += x2;              s3 += x3;
        a0 = fmaf(x0, h0, a0); a1 = fmaf(x1, h1, a1); a2 = fmaf(x2, h2, a2); a3 = fmaf(x3, h3, a3);
    }
    for (; t < deg; t++) {
        int i0 = __ldg(bkt + t);
        float e0 = __ldg(&g_el[i0 * 4 + hh]) + er_h;
        float h0 = __ldg(&g_h[(size_t)i0 * HD + lane]);
        e0 = (e0 > 0.f) ? e0 : NEG_SLOPE * e0;
        float x0 = __expf(e0);
        s0 += x0;
        a0 = fmaf(x0, h0, a0);
    }
    float s = (s0 + s1) + (s2 + s3);
    float acc = (a0 + a1) + (a2 + a3);
    float v = acc / (s + 1e-9f);
    v = (v > 0.f) ? v : expm1f(v);    // ELU
    out[(size_t)gw * HD + lane] = v;
}

// ---------------- launch ----------------
extern "C" void kernel_launch(void* const* d_in, const int* in_sizes, int n_in,
                              void* d_out, int out_size)
{
    const float* x0 = (const float*)d_in[0];
    const float* x1 = (const float*)d_in[1];
    const float* x2 = (const float*)d_in[2];
    const float* W0 = (const float*)d_in[3];
    const float* b0 = (const float*)d_in[4];
    const float* W1 = (const float*)d_in[5];
    const float* b1 = (const float*)d_in[6];
    const float* W2 = (const float*)d_in[7];
    const float* b2 = (const float*)d_in[8];
    const float* attn_l = (const float*)d_in[9];
    const float* attn_r = (const float*)d_in[10];

    const int* src; const int* dst;
    if (n_in >= 17 && in_sizes[11] == NNODES) {  // setup_inputs dict order: type_mask at 11
        src = (const int*)d_in[15];
        dst = (const int*)d_in[16];
    } else {                                     // reference arg order: idx0..idx2 at 11..13
        src = (const int*)d_in[14];
        dst = (const int*)d_in[15];
    }
    float* out = (float*)d_out;

    const int TB = 256;
    embed_kernel<<<3 * BLKS_PER_TYPE, TB>>>(x0, x1, x2, W0, b0, W1, b1, W2, b2,
                                            attn_l, attn_r);
    scatter_kernel<<<(NEDGES / 4 + TB - 1) / TB, TB>>>(src, dst);
    agg_kernel<<<(NNODES * 32 + TB - 1) / TB, TB>>>(out);
}

// round 11
// speedup vs baseline: 1.1838x; 1.0844x over previous
#include <cuda_runtime.h>
#include <cstdint>
#include <math.h>

#define NNODES   96000
#define NPERTYPE 32000
#define NEDGES   1536000
#define HD       32            // H*D
#define NEG_SLOPE 0.2f
#define BUCKET_CAP 64          // max in-degree capacity (Poisson(16): P(>64) ~ 1e-20)
#define ROWS_PER_BLK 128
#define EMBED_BLKS   750       // 3 types * 250
#define SCATTER_BLKS 750       // 8 edges per thread
#define XS_STRIDE 36           // 16B-aligned float4 stores; reads conflict-free

// ---------------- scratch (static device globals; no allocation) ----------------
// g_count starts zero (static init) and is RESET TO ZERO by agg_kernel at the end of
// every launch, so each launch's scatter sees zeros without an explicit zeroing pass.
__device__ float g_h [(size_t)NNODES * HD];          // [N,32] embedded features
__device__ float g_el[(size_t)NNODES * 4];           // [N,H]
__device__ float g_er[(size_t)NNODES * 4];           // [N,H]
__device__ int   g_count[NNODES];                    // in-degree (atomic cursor)
__device__ int   g_bucket[(size_t)NNODES * BUCKET_CAP]; // src ids grouped by dst

// ---------------- cp.async helpers ----------------
__device__ __forceinline__ void cp_async16(void* smem_ptr, const void* gptr) {
    uint32_t sa = (uint32_t)__cvta_generic_to_shared(smem_ptr);
    asm volatile("cp.async.cg.shared.global [%0], [%1], 16;" :: "r"(sa), "l"(gptr));
}
__device__ __forceinline__ void cp_commit() {
    asm volatile("cp.async.commit_group;");
}
__device__ __forceinline__ void cp_wait1() {
    asm volatile("cp.async.wait_group 1;");
}
__device__ __forceinline__ void cp_wait0() {
    asm volatile("cp.async.wait_group 0;");
}

// ---------------- embed tile: block-wide double-buffered cp.async (R9-proven) ----------
// Block: 256 threads = 8 warps, 128 rows. Warp w: rows [16w, 16w+16).
// Thread: rgrp=lane>>2 (rows 16w+rgrp, 16w+rgrp+8), cgrp=lane&3 (8 cols == head cgrp).
// K chunked by 32; chunk staged via cp.async (4x 16B per thread) into xs[buf][128][36].
template<int K>
__device__ __forceinline__ void embed_tile(
    float (* __restrict__ xs)[ROWS_PER_BLK * XS_STRIDE],
    const float* __restrict__ x,            // type-local [NPERTYPE, K]
    const float* __restrict__ W,            // [K, 32]
    const float* __restrict__ b,            // [32]
    const float* __restrict__ attn_l, const float* __restrict__ attn_r,
    int type_row_base, int grow_base)
{
    constexpr int NC = K / 32;              // chunks
    const int t = threadIdx.x;
    const int warp = t >> 5, lane = t & 31;
    const int rgrp = lane >> 2, cgrp = lane & 3;
    const int R0 = warp * 16 + rgrp;        // rows R0 and R0+8

    auto stage = [&](int buf, int k0) {
        #pragma unroll
        for (int q = 0; q < 4; q++) {
            int idx = t + 256 * q;
            int row = idx >> 3, c4 = (idx & 7) * 4;
            cp_async16(&xs[buf][row * XS_STRIDE + c4],
                       &x[(size_t)(type_row_base + row) * K + k0 + c4]);
        }
        cp_commit();
    };

    float4 bv0 = __ldg((const float4*)b + cgrp * 2);
    float4 bv1 = __ldg((const float4*)b + cgrp * 2 + 1);
    float acc[2][8];
    #pragma unroll
    for (int i = 0; i < 2; i++) {
        acc[i][0] = bv0.x; acc[i][1] = bv0.y; acc[i][2] = bv0.z; acc[i][3] = bv0.w;
        acc[i][4] = bv1.x; acc[i][5] = bv1.y; acc[i][6] = bv1.z; acc[i][7] = bv1.w;
    }

    stage(0, 0);

    #pragma unroll
    for (int c = 0; c < NC; c++) {
        if (c + 1 < NC) stage((c + 1) & 1, (c + 1) * 32);   // buffer last read in chunk c-1 (synced)
        if (c + 1 < NC) cp_wait1(); else cp_wait0();        // chunk c data arrived
        __syncthreads();

        const float* xb = xs[c & 1];
        #pragma unroll 8
        for (int kk = 0; kk < 32; kk++) {
            float4 w0 = __ldg((const float4*)(W + (size_t)(c * 32 + kk) * HD) + cgrp * 2);
            float4 w1 = __ldg((const float4*)(W + (size_t)(c * 32 + kk) * HD) + cgrp * 2 + 1);
            #pragma unroll
            for (int i = 0; i < 2; i++) {
                float xv = xb[(R0 + i * 8) * XS_STRIDE + kk];
                acc[i][0] = fmaf(xv, w0.x, acc[i][0]);
                acc[i][1] = fmaf(xv, w0.y, acc[i][1]);
                acc[i][2] = fmaf(xv, w0.z, acc[i][2]);
                acc[i][3] = fmaf(xv, w0.w, acc[i][3]);
                acc[i][4] = fmaf(xv, w1.x, acc[i][4]);
                acc[i][5] = fmaf(xv, w1.y, acc[i][5]);
                acc[i][6] = fmaf(xv, w1.z, acc[i][6]);
                acc[i][7] = fmaf(xv, w1.w, acc[i][7]);
            }
        }
        __syncthreads();
    }

    // epilogue: h store + thread-local el/er (this thread's 8 cols == head cgrp)
    float4 al0 = __ldg((const float4*)attn_l + cgrp * 2);
    float4 al1 = __ldg((const float4*)attn_l + cgrp * 2 + 1);
    float4 ar0 = __ldg((const float4*)attn_r + cgrp * 2);
    float4 ar1 = __ldg((const float4*)attn_r + cgrp * 2 + 1);
    #pragma unroll
    for (int i = 0; i < 2; i++) {
        int grow = grow_base + R0 + i * 8;
        float4 v0 = make_float4(acc[i][0], acc[i][1], acc[i][2], acc[i][3]);
        float4 v1 = make_float4(acc[i][4], acc[i][5], acc[i][6], acc[i][7]);
        *(float4*)&g_h[(size_t)grow * HD + cgrp * 8]     = v0;
        *(float4*)&g_h[(size_t)grow * HD + cgrp * 8 + 4] = v1;
        float el = v0.x * al0.x + v0.y * al0.y + v0.z * al0.z + v0.w * al0.w
                 + v1.x * al1.x + v1.y * al1.y + v1.z * al1.z + v1.w * al1.w;
        float er = v0.x * ar0.x + v0.y * ar0.y + v0.z * ar0.z + v0.w * ar0.w
                 + v1.x * ar1.x + v1.y * ar1.y + v1.z * ar1.z + v1.w * ar1.w;
        g_el[grow * 4 + cgrp] = el;
        g_er[grow * 4 + cgrp] = er;
    }
}

// ---------------- kernel 1: FUSED embed + edge scatter ----------------
// Blocks [0, 750): embed (role by blockIdx%3 type interleave).
// Blocks [750, 1500): scatter 8 edges/thread into fixed-capacity buckets.
// Independent work co-resident on the SMs: scatter's atomics/stores fill embed's
// latency bubbles. g_count is already zero at launch start (reset by prior agg).
__global__ void __launch_bounds__(256) fused_embed_scatter(
    const float* __restrict__ x0, const float* __restrict__ x1, const float* __restrict__ x2,
    const float* __restrict__ W0, const float* __restrict__ b0,
    const float* __restrict__ W1, const float* __restrict__ b1,
    const float* __restrict__ W2, const float* __restrict__ b2,
    const float* __restrict__ attn_l, const float* __restrict__ attn_r,
    const int* __restrict__ src, const int* __restrict__ dst)
{
    __shared__ float xs[2][ROWS_PER_BLK * XS_STRIDE];

    if (blockIdx.x < EMBED_BLKS) {
        int type = blockIdx.x % 3;          // interleave types for load balance
        int tb   = blockIdx.x / 3;
        int type_row_base = tb * ROWS_PER_BLK;
        int grow_base = type * NPERTYPE + type_row_base;

        if (type == 0)      embed_tile<128>(xs, x0, W0, b0, attn_l, attn_r, type_row_base, grow_base);
        else if (type == 1) embed_tile<64> (xs, x1, W1, b1, attn_l, attn_r, type_row_base, grow_base);
        else                embed_tile<32> (xs, x2, W2, b2, attn_l, attn_r, type_row_base, grow_base);
    } else {
        // scatter role: 8 edges per thread (2x int4)
        int sb = blockIdx.x - EMBED_BLKS;
        int base4 = (sb * 256 + threadIdx.x) * 2;        // int4 index; 2 per thread
        #pragma unroll
        for (int q = 0; q < 2; q++) {
            int i4 = base4 + q;
            if (i4 * 4 < NEDGES) {
                int4 s = __ldg((const int4*)src + i4);
                int4 d = __ldg((const int4*)dst + i4);
                int p;
                p = atomicAdd(&g_count[d.x], 1); if (p < BUCKET_CAP) g_bucket[(size_t)d.x * BUCKET_CAP + p] = s.x;
                p = atomicAdd(&g_count[d.y], 1); if (p < BUCKET_CAP) g_bucket[(size_t)d.y * BUCKET_CAP + p] = s.y;
                p = atomicAdd(&g_count[d.z], 1); if (p < BUCKET_CAP) g_bucket[(size_t)d.z * BUCKET_CAP + p] = s.z;
                p = atomicAdd(&g_count[d.w], 1); if (p < BUCKET_CAP) g_bucket[(size_t)d.w * BUCKET_CAP + p] = s.w;
            }
        }
    }
}

// ---------------- kernel 2: warp-per-dst softmax aggregation + ELU ----------------
// exp without max-subtraction (|e| small, softmax shift-invariant); 8-wide pipeline.
// Resets g_count to zero for the next launch.
__global__ void agg_kernel(float* __restrict__ out) {
    int gw   = (blockIdx.x * blockDim.x + threadIdx.x) >> 5;
    int lane = threadIdx.x & 31;
    if (gw >= NNODES) return;

    int deg = g_count[gw];
    deg = (deg > BUCKET_CAP) ? BUCKET_CAP : deg;
    const int hh = lane >> 3;
    const float er_h = g_er[gw * 4 + hh];
    const int* __restrict__ bkt = g_bucket + (size_t)gw * BUCKET_CAP;

    float s0 = 0.f, s1 = 0.f, s2 = 0.f, s3 = 0.f;
    float a0 = 0.f, a1 = 0.f, a2 = 0.f, a3 = 0.f;
    int t = 0;
    for (; t + 7 < deg; t += 8) {                        // deg ~ Poisson(16): usually 2 iters
        int4 iA = __ldg((const int4*)(bkt + t));
        int4 iB = __ldg((const int4*)(bkt + t + 4));
        float e0 = __ldg(&g_el[iA.x * 4 + hh]) + er_h;
        float e1 = __ldg(&g_el[iA.y * 4 + hh]) + er_h;
        float e2 = __ldg(&g_el[iA.z * 4 + hh]) + er_h;
        float e3 = __ldg(&g_el[iA.w * 4 + hh]) + er_h;
        float e4 = __ldg(&g_el[iB.x * 4 + hh]) + er_h;
        float e5 = __ldg(&g_el[iB.y * 4 + hh]) + er_h;
        float e6 = __ldg(&g_el[iB.z * 4 + hh]) + er_h;
        float e7 = __ldg(&g_el[iB.w * 4 + hh]) + er_h;
        float h0 = __ldg(&g_h[(size_t)iA.x * HD + lane]);
        float h1 = __ldg(&g_h[(size_t)iA.y * HD + lane]);
        float h2 = __ldg(&g_h[(size_t)iA.z * HD + lane]);
        float h3 = __ldg(&g_h[(size_t)iA.w * HD + lane]);
        float h4 = __ldg(&g_h[(size_t)iB.x * HD + lane]);
        float h5 = __ldg(&g_h[(size_t)iB.y * HD + lane]);
        float h6 = __ldg(&g_h[(size_t)iB.z * HD + lane]);
        float h7 = __ldg(&g_h[(size_t)iB.w * HD + lane]);
        e0 = (e0 > 0.f) ? e0 : NEG_SLOPE * e0;  e1 = (e1 > 0.f) ? e1 : NEG_SLOPE * e1;
        e2 = (e2 > 0.f) ? e2 : NEG_SLOPE * e2;  e3 = (e3 > 0.f) ? e3 : NEG_SLOPE * e3;
        e4 = (e4 > 0.f) ? e4 : NEG_SLOPE * e4;  e5 = (e5 > 0.f) ? e5 : NEG_SLOPE * e5;
        e6 = (e6 > 0.f) ? e6 : NEG_SLOPE * e6;  e7 = (e7 > 0.f) ? e7 : NEG_SLOPE * e7;
        float x0 = __expf(e0), x1 = __expf(e1), x2 = __expf(e2), x3 = __expf(e3);
        float x4 = __expf(e4), x5 = __expf(e5), x6 = __expf(e6), x7 = __expf(e7);
        s0 += x0 + x4;          s1 += x1 + x5;          s2 += x2 + x6;          s3 += x3 + x7;
        a0 = fmaf(x0, h0, a0);  a1 = fmaf(x1, h1, a1);  a2 = fmaf(x2, h2, a2);  a3 = fmaf(x3, h3, a3);
        a0 = fmaf(x4, h4, a0);  a1 = fmaf(x5, h5, a1);  a2 = fmaf(x6, h6, a2);  a3 = fmaf(x7, h7, a3);
    }
    for (; t + 3 < deg; t += 4) {
        int4 ii = __ldg((const int4*)(bkt + t));
        float e0 = __ldg(&g_el[ii.x * 4 + hh]) + er_h;
        float e1 = __ldg(&g_el[ii.y * 4 + hh]) + er_h;
        float e2 = __ldg(&g_el[ii.z * 4 + hh]) + er_h;
        float e3 = __ldg(&g_el[ii.w * 4 + hh]) + er_h;
        float h0 = __ldg(&g_h[(size_t)ii.x * HD + lane]);
        float h1 = __ldg(&g_h[(size_t)ii.y * HD + lane]);
        float h2 = __ldg(&g_h[(size_t)ii.z * HD + lane]);
        float h3 = __ldg(&g_h[(size_t)ii.w * HD + lane]);
        e0 = (e0 > 0.f) ? e0 : NEG_SLOPE * e0;  e1 = (e1 > 0.f) ? e1 : NEG_SLOPE * e1;
        e2 = (e2 > 0.f) ? e2 : NEG_SLOPE * e2;  e3 = (e3 > 0.f) ? e3 : NEG_SLOPE * e3;
        float x0 = __expf(e0), x1 = __expf(e1), x2 = __expf(e2), x3 = __expf(e3);
        s0 += x0;               s1 += x1;               s2 += x2;               s3 += x3;
        a0 = fmaf(x0, h0, a0);  a1 = fmaf(x1, h1, a1);  a2 = fmaf(x2, h2, a2);  a3 = fmaf(x3, h3, a3);
    }
    for (; t < deg; t++) {
        int i0 = __ldg(bkt + t);
        float e0 = __ldg(&g_el[i0 * 4 + hh]) + er_h;
        float h0 = __ldg(&g_h[(size_t)i0 * HD + lane]);
        e0 = (e0 > 0.f) ? e0 : NEG_SLOPE * e0;
        float x0 = __expf(e0);
        s0 += x0;
        a0 = fmaf(x0, h0, a0);
    }
    float s = (s0 + s1) + (s2 + s3);
    float acc = (a0 + a1) + (a2 + a3);
    float v = acc / (s + 1e-9f);
    v = (v > 0.f) ? v : expm1f(v);    // ELU
    out[(size_t)gw * HD + lane] = v;

    if (lane == 0) g_count[gw] = 0;   // reset counters for next launch (scatter precondition)
}

// ---------------- launch ----------------
extern "C" void kernel_launch(void* const* d_in, const int* in_sizes, int n_in,
                              void* d_out, int out_size)
{
    const float* x0 = (const float*)d_in[0];
    const float* x1 = (const float*)d_in[1];
    const float* x2 = (const float*)d_in[2];
    const float* W0 = (const float*)d_in[3];
    const float* b0 = (const float*)d_in[4];
    const float* W1 = (const float*)d_in[5];
    const float* b1 = (const float*)d_in[6];
    const float* W2 = (const float*)d_in[7];
    const float* b2 = (const float*)d_in[8];
    const float* attn_l = (const float*)d_in[9];
    const float* attn_r = (const float*)d_in[10];

    const int* src; const int* dst;
    if (n_in >= 17 && in_sizes[11] == NNODES) {  // setup_inputs dict order: type_mask at 11
        src = (const int*)d_in[15];
        dst = (const int*)d_in[16];
    } else {                                     // reference arg order: idx0..idx2 at 11..13
        src = (const int*)d_in[14];
        dst = (const int*)d_in[15];
    }
    float* out = (float*)d_out;

    const int TB = 256;
    fused_embed_scatter<<<EMBED_BLKS + SCATTER_BLKS, TB>>>(
        x0, x1, x2, W0, b0, W1, b1, W2, b2, attn_l, attn_r, src, dst);
    agg_kernel<<<(NNODES * 32 + TB - 1) / TB, TB>>>(out);
}

// round 12
// speedup vs baseline: 1.2006x; 1.0142x over previous
#include <cuda_runtime.h>
#include <cstdint>
#include <math.h>

#define NNODES   96000
#define NPERTYPE 32000
#define NEDGES   1536000
#define HD       32            // H*D
#define ROW      40            // combined row: 32 h + 4 el + 4 er
#define NEG_SLOPE 0.2f
#define LOG2E    1.4426950408889634f
#define BUCKET_CAP 64          // max in-degree capacity (Poisson(16): P(>64) ~ 1e-20)
#define ROWS_PER_BLK 128
#define EMBED_BLKS   750       // 3 types * 250
#define SCATTER_BLKS 750       // 8 edges per thread
#define XS_STRIDE 36           // 16B-aligned float4 stores; reads conflict-free

// ---------------- scratch (static device globals; no allocation) ----------------
// g_count starts zero (static init) and is RESET TO ZERO by agg_kernel at the end of
// every launch, so each launch's scatter sees zeros without an explicit zeroing pass.
__device__ float g_hx[(size_t)NNODES * ROW];         // [N,40]: h[32], el'[4], er'[4] (el/er pre-scaled by log2e)
__device__ int   g_count[NNODES];                    // in-degree (atomic cursor)
__device__ int   g_bucket[(size_t)NNODES * BUCKET_CAP]; // src*ROW offsets grouped by dst

// ---------------- cp.async helpers ----------------
__device__ __forceinline__ void cp_async16(void* smem_ptr, const void* gptr) {
    uint32_t sa = (uint32_t)__cvta_generic_to_shared(smem_ptr);
    asm volatile("cp.async.cg.shared.global [%0], [%1], 16;" :: "r"(sa), "l"(gptr));
}
__device__ __forceinline__ void cp_commit() {
    asm volatile("cp.async.commit_group;");
}
__device__ __forceinline__ void cp_wait1() {
    asm volatile("cp.async.wait_group 1;");
}
__device__ __forceinline__ void cp_wait0() {
    asm volatile("cp.async.wait_group 0;");
}
__device__ __forceinline__ float ex2f(float x) {
    float r;
    asm("ex2.approx.ftz.f32 %0, %1;" : "=f"(r) : "f"(x));
    return r;
}

// ---------------- embed tile: block-wide double-buffered cp.async ----------
// Block: 256 threads = 8 warps, 128 rows. Warp w: rows [16w, 16w+16).
// Thread: rgrp=lane>>2 (rows 16w+rgrp, 16w+rgrp+8), cgrp=lane&3 (8 cols == head cgrp).
template<int K>
__device__ __forceinline__ void embed_tile(
    float (* __restrict__ xs)[ROWS_PER_BLK * XS_STRIDE],
    const float* __restrict__ x,            // type-local [NPERTYPE, K]
    const float* __restrict__ W,            // [K, 32]
    const float* __restrict__ b,            // [32]
    const float* __restrict__ attn_l, const float* __restrict__ attn_r,
    int type_row_base, int grow_base)
{
    constexpr int NC = K / 32;              // chunks
    const int t = threadIdx.x;
    const int warp = t >> 5, lane = t & 31;
    const int rgrp = lane >> 2, cgrp = lane & 3;
    const int R0 = warp * 16 + rgrp;        // rows R0 and R0+8

    auto stage = [&](int buf, int k0) {
        #pragma unroll
        for (int q = 0; q < 4; q++) {
            int idx = t + 256 * q;
            int row = idx >> 3, c4 = (idx & 7) * 4;
            cp_async16(&xs[buf][row * XS_STRIDE + c4],
                       &x[(size_t)(type_row_base + row) * K + k0 + c4]);
        }
        cp_commit();
    };

    float4 bv0 = __ldg((const float4*)b + cgrp * 2);
    float4 bv1 = __ldg((const float4*)b + cgrp * 2 + 1);
    float acc[2][8];
    #pragma unroll
    for (int i = 0; i < 2; i++) {
        acc[i][0] = bv0.x; acc[i][1] = bv0.y; acc[i][2] = bv0.z; acc[i][3] = bv0.w;
        acc[i][4] = bv1.x; acc[i][5] = bv1.y; acc[i][6] = bv1.z; acc[i][7] = bv1.w;
    }

    stage(0, 0);

    #pragma unroll
    for (int c = 0; c < NC; c++) {
        if (c + 1 < NC) stage((c + 1) & 1, (c + 1) * 32);   // buffer last read in chunk c-1 (synced)
        if (c + 1 < NC) cp_wait1(); else cp_wait0();        // chunk c data arrived
        __syncthreads();

        const float* xb = xs[c & 1];
        #pragma unroll 8
        for (int kk = 0; kk < 32; kk++) {
            float4 w0 = __ldg((const float4*)(W + (size_t)(c * 32 + kk) * HD) + cgrp * 2);
            float4 w1 = __ldg((const float4*)(W + (size_t)(c * 32 + kk) * HD) + cgrp * 2 + 1);
            #pragma unroll
            for (int i = 0; i < 2; i++) {
                float xv = xb[(R0 + i * 8) * XS_STRIDE + kk];
                acc[i][0] = fmaf(xv, w0.x, acc[i][0]);
                acc[i][1] = fmaf(xv, w0.y, acc[i][1]);
                acc[i][2] = fmaf(xv, w0.z, acc[i][2]);
                acc[i][3] = fmaf(xv, w0.w, acc[i][3]);
                acc[i][4] = fmaf(xv, w1.x, acc[i][4]);
                acc[i][5] = fmaf(xv, w1.y, acc[i][5]);
                acc[i][6] = fmaf(xv, w1.z, acc[i][6]);
                acc[i][7] = fmaf(xv, w1.w, acc[i][7]);
            }
        }
        __syncthreads();
    }

    // epilogue: combined row store: h + pre-scaled el'/er' (this thread's 8 cols == head cgrp)
    float4 al0 = __ldg((const float4*)attn_l + cgrp * 2);
    float4 al1 = __ldg((const float4*)attn_l + cgrp * 2 + 1);
    float4 ar0 = __ldg((const float4*)attn_r + cgrp * 2);
    float4 ar1 = __ldg((const float4*)attn_r + cgrp * 2 + 1);
    #pragma unroll
    for (int i = 0; i < 2; i++) {
        int grow = grow_base + R0 + i * 8;
        float* rowp = g_hx + (size_t)grow * ROW;
        float4 v0 = make_float4(acc[i][0], acc[i][1], acc[i][2], acc[i][3]);
        float4 v1 = make_float4(acc[i][4], acc[i][5], acc[i][6], acc[i][7]);
        *(float4*)(rowp + cgrp * 8)     = v0;
        *(float4*)(rowp + cgrp * 8 + 4) = v1;
        float el = v0.x * al0.x + v0.y * al0.y + v0.z * al0.z + v0.w * al0.w
                 + v1.x * al1.x + v1.y * al1.y + v1.z * al1.z + v1.w * al1.w;
        float er = v0.x * ar0.x + v0.y * ar0.y + v0.z * ar0.z + v0.w * ar0.w
                 + v1.x * ar1.x + v1.y * ar1.y + v1.z * ar1.z + v1.w * ar1.w;
        rowp[32 + cgrp] = el * LOG2E;   // pre-scaled so agg uses raw EX2
        rowp[36 + cgrp] = er * LOG2E;
    }
}

// ---------------- kernel 1: FUSED embed + edge scatter ----------------
// Blocks [0, 750): embed. Blocks [750, 1500): scatter 8 edges/thread.
// g_count is already zero at launch start (reset by prior agg).
__global__ void __launch_bounds__(256) fused_embed_scatter(
    const float* __restrict__ x0, const float* __restrict__ x1, const float* __restrict__ x2,
    const float* __restrict__ W0, const float* __restrict__ b0,
    const float* __restrict__ W1, const float* __restrict__ b1,
    const float* __restrict__ W2, const float* __restrict__ b2,
    const float* __restrict__ attn_l, const float* __restrict__ attn_r,
    const int* __restrict__ src, const int* __restrict__ dst)
{
    __shared__ float xs[2][ROWS_PER_BLK * XS_STRIDE];

    if (blockIdx.x < EMBED_BLKS) {
        int type = blockIdx.x % 3;          // interleave types for load balance
        int tb   = blockIdx.x / 3;
        int type_row_base = tb * ROWS_PER_BLK;
        int grow_base = type * NPERTYPE + type_row_base;

        if (type == 0)      embed_tile<128>(xs, x0, W0, b0, attn_l, attn_r, type_row_base, grow_base);
        else if (type == 1) embed_tile<64> (xs, x1, W1, b1, attn_l, attn_r, type_row_base, grow_base);
        else                embed_tile<32> (xs, x2, W2, b2, attn_l, attn_r, type_row_base, grow_base);
    } else {
        // scatter role: 8 edges per thread (2x int4); store src*ROW (agg-ready offset)
        int sb = blockIdx.x - EMBED_BLKS;
        int base4 = (sb * 256 + threadIdx.x) * 2;        // int4 index; 2 per thread
        #pragma unroll
        for (int q = 0; q < 2; q++) {
            int i4 = base4 + q;
            if (i4 * 4 < NEDGES) {
                int4 s = __ldg((const int4*)src + i4);
                int4 d = __ldg((const int4*)dst + i4);
                int p;
                p = atomicAdd(&g_count[d.x], 1); if (p < BUCKET_CAP) g_bucket[(size_t)d.x * BUCKET_CAP + p] = s.x * ROW;
                p = atomicAdd(&g_count[d.y], 1); if (p < BUCKET_CAP) g_bucket[(size_t)d.y * BUCKET_CAP + p] = s.y * ROW;
                p = atomicAdd(&g_count[d.z], 1); if (p < BUCKET_CAP) g_bucket[(size_t)d.z * BUCKET_CAP + p] = s.z * ROW;
                p = atomicAdd(&g_count[d.w], 1); if (p < BUCKET_CAP) g_bucket[(size_t)d.w * BUCKET_CAP + p] = s.w * ROW;
            }
        }
    }
}

// ---------------- kernel 2: warp-per-dst softmax aggregation + ELU ----------------
// el'/er' are pre-scaled by log2e -> single EX2 per edge. 8-wide pipeline.
// Resets g_count to zero for the next launch.
__global__ void agg_kernel(float* __restrict__ out) {
    int gw   = (blockIdx.x * blockDim.x + threadIdx.x) >> 5;
    int lane = threadIdx.x & 31;
    if (gw >= NNODES) return;

    int deg = g_count[gw];
    deg = (deg > BUCKET_CAP) ? BUCKET_CAP : deg;
    const int hh = lane >> 3;
    const float er_h = g_hx[(size_t)gw * ROW + 36 + hh];     // pre-scaled er'
    const int* __restrict__ bkt = g_bucket + (size_t)gw * BUCKET_CAP;

    // loop-invariant gather bases: one for this lane's h dim, one for this lane's el' slot
    const float* __restrict__ hbase = g_hx + lane;            // + off -> h[src][lane]
    const float* __restrict__ ebase = g_hx + 32 + hh;         // + off -> el'[src][hh]

    float s0 = 0.f, s1 = 0.f, s2 = 0.f, s3 = 0.f;
    float a0 = 0.f, a1 = 0.f, a2 = 0.f, a3 = 0.f;
    int t = 0;
    for (; t + 7 < deg; t += 8) {                        // deg ~ Poisson(16): usually 2 iters
        int4 iA = __ldg((const int4*)(bkt + t));
        int4 iB = __ldg((const int4*)(bkt + t + 4));
        float e0 = __ldg(ebase + iA.x) + er_h;
        float e1 = __ldg(ebase + iA.y) + er_h;
        float e2 = __ldg(ebase + iA.z) + er_h;
        float e3 = __ldg(ebase + iA.w) + er_h;
        float e4 = __ldg(ebase + iB.x) + er_h;
        float e5 = __ldg(ebase + iB.y) + er_h;
        float e6 = __ldg(ebase + iB.z) + er_h;
        float e7 = __ldg(ebase + iB.w) + er_h;
        float h0 = __ldg(hbase + iA.x);
        float h1 = __ldg(hbase + iA.y);
        float h2 = __ldg(hbase + iA.z);
        float h3 = __ldg(hbase + iA.w);
        float h4 = __ldg(hbase + iB.x);
        float h5 = __ldg(hbase + iB.y);
        float h6 = __ldg(hbase + iB.z);
        float h7 = __ldg(hbase + iB.w);
        float x0 = ex2f(fmaxf(e0, NEG_SLOPE * e0));
        float x1 = ex2f(fmaxf(e1, NEG_SLOPE * e1));
        float x2 = ex2f(fmaxf(e2, NEG_SLOPE * e2));
        float x3 = ex2f(fmaxf(e3, NEG_SLOPE * e3));
        float x4 = ex2f(fmaxf(e4, NEG_SLOPE * e4));
        float x5 = ex2f(fmaxf(e5, NEG_SLOPE * e5));
        float x6 = ex2f(fmaxf(e6, NEG_SLOPE * e6));
        float x7 = ex2f(fmaxf(e7, NEG_SLOPE * e7));
        s0 += x0 + x4;          s1 += x1 + x5;          s2 += x2 + x6;          s3 += x3 + x7;
        a0 = fmaf(x0, h0, a0);  a1 = fmaf(x1, h1, a1);  a2 = fmaf(x2, h2, a2);  a3 = fmaf(x3, h3, a3);
        a0 = fmaf(x4, h4, a0);  a1 = fmaf(x5, h5, a1);  a2 = fmaf(x6, h6, a2);  a3 = fmaf(x7, h7, a3);
    }
    for (; t + 3 < deg; t += 4) {
        int4 ii = __ldg((const int4*)(bkt + t));
        float e0 = __ldg(ebase + ii.x) + er_h;
        float e1 = __ldg(ebase + ii.y) + er_h;
        float e2 = __ldg(ebase + ii.z) + er_h;
        float e3 = __ldg(ebase + ii.w) + er_h;
        float h0 = __ldg(hbase + ii.x);
        float h1 = __ldg(hbase + ii.y);
        float h2 = __ldg(hbase + ii.z);
        float h3 = __ldg(hbase + ii.w);
        float x0 = ex2f(fmaxf(e0, NEG_SLOPE * e0));
        float x1 = ex2f(fmaxf(e1, NEG_SLOPE * e1));
        float x2 = ex2f(fmaxf(e2, NEG_SLOPE * e2));
        float x3 = ex2f(fmaxf(e3, NEG_SLOPE * e3));
        s0 += x0;               s1 += x1;               s2 += x2;               s3 += x3;
        a0 = fmaf(x0, h0, a0);  a1 = fmaf(x1, h1, a1);  a2 = fmaf(x2, h2, a2);  a3 = fmaf(x3, h3, a3);
    }
    for (; t < deg; t++) {
        int i0 = __ldg(bkt + t);
        float e0 = __ldg(ebase + i0) + er_h;
        float h0 = __ldg(hbase + i0);
        float x0 = ex2f(fmaxf(e0, NEG_SLOPE * e0));
        s0 += x0;
        a0 = fmaf(x0, h0, a0);
    }
    float s = (s0 + s1) + (s2 + s3);
    float acc = (a0 + a1) + (a2 + a3);
    float v = __fdividef(acc, s + 1e-9f);
    v = (v > 0.f) ? v : expm1f(v);    // ELU
    out[(size_t)gw * HD + lane] = v;

    if (lane == 0) g_count[gw] = 0;   // reset counters for next launch (scatter precondition)
}

// ---------------- launch ----------------
extern "C" void kernel_launch(void* const* d_in, const int* in_sizes, int n_in,
                              void* d_out, int out_size)
{
    const float* x0 = (const float*)d_in[0];
    const float* x1 = (const float*)d_in[1];
    const float* x2 = (const float*)d_in[2];
    const float* W0 = (const float*)d_in[3];
    const float* b0 = (const float*)d_in[4];
    const float* W1 = (const float*)d_in[5];
    const float* b1 = (const float*)d_in[6];
    const float* W2 = (const float*)d_in[7];
    const float* b2 = (const float*)d_in[8];
    const float* attn_l = (const float*)d_in[9];
    const float* attn_r = (const float*)d_in[10];

    const int* src; const int* dst;
    if (n_in >= 17 && in_sizes[11] == NNODES) {  // setup_inputs dict order: type_mask at 11
        src = (const int*)d_in[15];
        dst = (const int*)d_in[16];
    } else {                                     // reference arg order: idx0..idx2 at 11..13
        src = (const int*)d_in[14];
        dst = (const int*)d_in[15];
    }
    float* out = (float*)d_out;

    const int TB = 256;
    fused_embed_scatter<<<EMBED_BLKS + SCATTER_BLKS, TB>>>(
        x0, x1, x2, W0, b0, W1, b1, W2, b2, attn_l, attn_r, src, dst);
    agg_kernel<<<(NNODES * 32 + TB - 1) / TB, TB>>>(out);
}

// round 13
// speedup vs baseline: 1.3551x; 1.1287x over previous
#include <cuda_runtime.h>
#include <cstdint>
#include <math.h>

#define NNODES   96000
#define NPERTYPE 32000
#define NEDGES   1536000
#define HD       32            // H*D
#define ROW      64            // padded row: h[32], el'[4]@32, er'[4]@36, pad; 256B-aligned
#define NEG_SLOPE 0.2f
#define LOG2E    1.4426950408889634f
#define BUCKET_CAP 64          // max in-degree capacity (Poisson(16): P(>64) ~ 1e-20)
#define ROWS_PER_BLK 128
#define EMBED_BLKS   750       // 3 types * 250
#define SCATTER_BLKS 750       // 8 edges per thread
#define XS_STRIDE 36           // 16B-aligned float4 stores; reads conflict-free

// ---------------- scratch (static device globals; no allocation) ----------------
// g_count starts zero (static init) and is RESET TO ZERO by agg_kernel at the end of
// every launch, so each launch's scatter sees zeros without an explicit zeroing pass.
__device__ float g_hx[(size_t)NNODES * ROW];         // [N,64]: h[32], el'[4], er'[4] (pre-scaled by log2e)
__device__ int   g_count[NNODES];                    // in-degree (atomic cursor)
__device__ int   g_bucket[(size_t)NNODES * BUCKET_CAP]; // src*ROW offsets grouped by dst

// ---------------- helpers ----------------
__device__ __forceinline__ void cp_async16(void* smem_ptr, const void* gptr) {
    uint32_t sa = (uint32_t)__cvta_generic_to_shared(smem_ptr);
    asm volatile("cp.async.cg.shared.global [%0], [%1], 16;" :: "r"(sa), "l"(gptr));
}
__device__ __forceinline__ void cp_commit() {
    asm volatile("cp.async.commit_group;");
}
__device__ __forceinline__ void cp_wait1() {
    asm volatile("cp.async.wait_group 1;");
}
__device__ __forceinline__ void cp_wait0() {
    asm volatile("cp.async.wait_group 0;");
}
__device__ __forceinline__ float ex2f(float x) {
    float r;
    asm("ex2.approx.ftz.f32 %0, %1;" : "=f"(r) : "f"(x));
    return r;
}

// ---------------- embed tile: block-wide double-buffered cp.async ----------
// Block: 256 threads = 8 warps, 128 rows. Warp w: rows [16w, 16w+16).
// Thread: rgrp=lane>>2 (rows 16w+rgrp, 16w+rgrp+8), cgrp=lane&3 (8 cols == head cgrp).
template<int K>
__device__ __forceinline__ void embed_tile(
    float (* __restrict__ xs)[ROWS_PER_BLK * XS_STRIDE],
    const float* __restrict__ x,            // type-local [NPERTYPE, K]
    const float* __restrict__ W,            // [K, 32]
    const float* __restrict__ b,            // [32]
    const float* __restrict__ attn_l, const float* __restrict__ attn_r,
    int type_row_base, int grow_base)
{
    constexpr int NC = K / 32;              // chunks
    const int t = threadIdx.x;
    const int warp = t >> 5, lane = t & 31;
    const int rgrp = lane >> 2, cgrp = lane & 3;
    const int R0 = warp * 16 + rgrp;        // rows R0 and R0+8

    auto stage = [&](int buf, int k0) {
        #pragma unroll
        for (int q = 0; q < 4; q++) {
            int idx = t + 256 * q;
            int row = idx >> 3, c4 = (idx & 7) * 4;
            cp_async16(&xs[buf][row * XS_STRIDE + c4],
                       &x[(size_t)(type_row_base + row) * K + k0 + c4]);
        }
        cp_commit();
    };

    float4 bv0 = __ldg((const float4*)b + cgrp * 2);
    float4 bv1 = __ldg((const float4*)b + cgrp * 2 + 1);
    float acc[2][8];
    #pragma unroll
    for (int i = 0; i < 2; i++) {
        acc[i][0] = bv0.x; acc[i][1] = bv0.y; acc[i][2] = bv0.z; acc[i][3] = bv0.w;
        acc[i][4] = bv1.x; acc[i][5] = bv1.y; acc[i][6] = bv1.z; acc[i][7] = bv1.w;
    }

    stage(0, 0);

    #pragma unroll
    for (int c = 0; c < NC; c++) {
        if (c + 1 < NC) stage((c + 1) & 1, (c + 1) * 32);   // buffer last read in chunk c-1 (synced)
        if (c + 1 < NC) cp_wait1(); else cp_wait0();        // chunk c data arrived
        __syncthreads();

        const float* xb = xs[c & 1];
        #pragma unroll 8
        for (int kk = 0; kk < 32; kk++) {
            float4 w0 = __ldg((const float4*)(W + (size_t)(c * 32 + kk) * HD) + cgrp * 2);
            float4 w1 = __ldg((const float4*)(W + (size_t)(c * 32 + kk) * HD) + cgrp * 2 + 1);
            #pragma unroll
            for (int i = 0; i < 2; i++) {
                float xv = xb[(R0 + i * 8) * XS_STRIDE + kk];
                acc[i][0] = fmaf(xv, w0.x, acc[i][0]);
                acc[i][1] = fmaf(xv, w0.y, acc[i][1]);
                acc[i][2] = fmaf(xv, w0.z, acc[i][2]);
                acc[i][3] = fmaf(xv, w0.w, acc[i][3]);
                acc[i][4] = fmaf(xv, w1.x, acc[i][4]);
                acc[i][5] = fmaf(xv, w1.y, acc[i][5]);
                acc[i][6] = fmaf(xv, w1.z, acc[i][6]);
                acc[i][7] = fmaf(xv, w1.w, acc[i][7]);
            }
        }
        __syncthreads();
    }

    // epilogue: combined row store: h + pre-scaled el'/er' (this thread's 8 cols == head cgrp)
    float4 al0 = __ldg((const float4*)attn_l + cgrp * 2);
    float4 al1 = __ldg((const float4*)attn_l + cgrp * 2 + 1);
    float4 ar0 = __ldg((const float4*)attn_r + cgrp * 2);
    float4 ar1 = __ldg((const float4*)attn_r + cgrp * 2 + 1);
    #pragma unroll
    for (int i = 0; i < 2; i++) {
        int grow = grow_base + R0 + i * 8;
        float* rowp = g_hx + (size_t)grow * ROW;
        float4 v0 = make_float4(acc[i][0], acc[i][1], acc[i][2], acc[i][3]);
        float4 v1 = make_float4(acc[i][4], acc[i][5], acc[i][6], acc[i][7]);
        *(float4*)(rowp + cgrp * 8)     = v0;
        *(float4*)(rowp + cgrp * 8 + 4) = v1;
        float el = v0.x * al0.x + v0.y * al0.y + v0.z * al0.z + v0.w * al0.w
                 + v1.x * al1.x + v1.y * al1.y + v1.z * al1.z + v1.w * al1.w;
        float er = v0.x * ar0.x + v0.y * ar0.y + v0.z * ar0.z + v0.w * ar0.w
                 + v1.x * ar1.x + v1.y * ar1.y + v1.z * ar1.z + v1.w * ar1.w;
        rowp[32 + cgrp] = el * LOG2E;   // pre-scaled so agg uses raw EX2
        rowp[36 + cgrp] = er * LOG2E;
    }
}

// ---------------- kernel 1: FUSED embed + edge scatter ----------------
__global__ void __launch_bounds__(256) fused_embed_scatter(
    const float* __restrict__ x0, const float* __restrict__ x1, const float* __restrict__ x2,
    const float* __restrict__ W0, const float* __restrict__ b0,
    const float* __restrict__ W1, const float* __restrict__ b1,
    const float* __restrict__ W2, const float* __restrict__ b2,
    const float* __restrict__ attn_l, const float* __restrict__ attn_r,
    const int* __restrict__ src, const int* __restrict__ dst)
{
    __shared__ float xs[2][ROWS_PER_BLK * XS_STRIDE];

    if (blockIdx.x < EMBED_BLKS) {
        int type = blockIdx.x % 3;          // interleave types for load balance
        int tb   = blockIdx.x / 3;
        int type_row_base = tb * ROWS_PER_BLK;
        int grow_base = type * NPERTYPE + type_row_base;

        if (type == 0)      embed_tile<128>(xs, x0, W0, b0, attn_l, attn_r, type_row_base, grow_base);
        else if (type == 1) embed_tile<64> (xs, x1, W1, b1, attn_l, attn_r, type_row_base, grow_base);
        else                embed_tile<32> (xs, x2, W2, b2, attn_l, attn_r, type_row_base, grow_base);
    } else {
        // scatter role: 8 edges per thread (2x int4); store src*ROW (agg-ready offset)
        int sb = blockIdx.x - EMBED_BLKS;
        int base4 = (sb * 256 + threadIdx.x) * 2;        // int4 index; 2 per thread
        #pragma unroll
        for (int q = 0; q < 2; q++) {
            int i4 = base4 + q;
            if (i4 * 4 < NEDGES) {
                int4 s = __ldg((const int4*)src + i4);
                int4 d = __ldg((const int4*)dst + i4);
                int p;
                p = atomicAdd(&g_count[d.x], 1); if (p < BUCKET_CAP) g_bucket[(size_t)d.x * BUCKET_CAP + p] = s.x << 6;
                p = atomicAdd(&g_count[d.y], 1); if (p < BUCKET_CAP) g_bucket[(size_t)d.y * BUCKET_CAP + p] = s.y << 6;
                p = atomicAdd(&g_count[d.z], 1); if (p < BUCKET_CAP) g_bucket[(size_t)d.z * BUCKET_CAP + p] = s.z << 6;
                p = atomicAdd(&g_count[d.w], 1); if (p < BUCKET_CAP) g_bucket[(size_t)d.w * BUCKET_CAP + p] = s.w << 6;
            }
        }
    }
}

// ---------------- kernel 2: group-per-edge softmax aggregation + ELU ----------------
// Warp = one dst node, split into 4 groups of 8 lanes. Each group processes ONE edge
// per step: lane loads float4 of h (8 lanes x 4 dims = 32 dims), e loaded per-lane
// (broadcast within half-group). One LDG.128 + one LDG + one EX2 serve 4 edges.
// Cross-group shfl reduction at the end. Resets g_count for the next launch.
__global__ void agg_kernel(float* __restrict__ out) {
    int gw   = (blockIdx.x * blockDim.x + threadIdx.x) >> 5;
    int lane = threadIdx.x & 31;
    if (gw >= NNODES) return;

    int deg = g_count[gw];
    deg = (deg > BUCKET_CAP) ? BUCKET_CAP : deg;
    const int g    = lane >> 3;         // edge-group 0..3
    const int sub  = lane & 7;          // lane within group
    const int hd4  = sub * 4;           // this lane's 4 h dims
    const int head = sub >> 1;          // head owning those dims
    const float er_h = g_hx[(size_t)gw * ROW + 36 + head];   // pre-scaled er'
    const int* __restrict__ bkt = g_bucket + (size_t)gw * BUCKET_CAP;

    float4 a = make_float4(0.f, 0.f, 0.f, 0.f);
    float s = 0.f;

    for (int t = 0; t < deg; t += 8) {
        // two 4-edge batches in flight per iteration
        int t0 = t + g, t1 = t + 4 + g;
        bool v0 = t0 < deg, v1 = t1 < deg;
        int off0 = __ldg(bkt + (v0 ? t0 : 0));
        int off1 = __ldg(bkt + (v1 ? t1 : 0));
        const float* r0 = g_hx + off0;
        const float* r1 = g_hx + off1;
        float  e0 = __ldg(r0 + 32 + head) + er_h;
        float  e1 = __ldg(r1 + 32 + head) + er_h;
        float4 h0 = __ldg((const float4*)(r0 + hd4));
        float4 h1 = __ldg((const float4*)(r1 + hd4));
        float x0 = ex2f(fmaxf(e0, NEG_SLOPE * e0));
        float x1 = ex2f(fmaxf(e1, NEG_SLOPE * e1));
        x0 = v0 ? x0 : 0.f;
        x1 = v1 ? x1 : 0.f;
        s += x0 + x1;
        a.x = fmaf(x0, h0.x, a.x);  a.y = fmaf(x0, h0.y, a.y);
        a.z = fmaf(x0, h0.z, a.z);  a.w = fmaf(x0, h0.w, a.w);
        a.x = fmaf(x1, h1.x, a.x);  a.y = fmaf(x1, h1.y, a.y);
        a.z = fmaf(x1, h1.z, a.z);  a.w = fmaf(x1, h1.w, a.w);
    }

    // reduce the 4 groups (xor 8, 16); s and a.{x,y,z,w}
    #pragma unroll
    for (int o = 8; o < 32; o <<= 1) {
        s   += __shfl_xor_sync(0xffffffffu, s,   o);
        a.x += __shfl_xor_sync(0xffffffffu, a.x, o);
        a.y += __shfl_xor_sync(0xffffffffu, a.y, o);
        a.z += __shfl_xor_sync(0xffffffffu, a.z, o);
        a.w += __shfl_xor_sync(0xffffffffu, a.w, o);
    }

    if (g == 0) {
        float inv = __fdividef(1.f, s + 1e-9f);
        float4 v;
        v.x = a.x * inv; v.y = a.y * inv; v.z = a.z * inv; v.w = a.w * inv;
        v.x = (v.x > 0.f) ? v.x : expm1f(v.x);
        v.y = (v.y > 0.f) ? v.y : expm1f(v.y);
        v.z = (v.z > 0.f) ? v.z : expm1f(v.z);
        v.w = (v.w > 0.f) ? v.w : expm1f(v.w);
        *(float4*)&out[(size_t)gw * HD + hd4] = v;
        if (sub == 0) g_count[gw] = 0;   // reset counters for next launch
    }
}

// ---------------- launch ----------------
extern "C" void kernel_launch(void* const* d_in, const int* in_sizes, int n_in,
                              void* d_out, int out_size)
{
    const float* x0 = (const float*)d_in[0];
    const float* x1 = (const float*)d_in[1];
    const float* x2 = (const float*)d_in[2];
    const float* W0 = (const float*)d_in[3];
    const float* b0 = (const float*)d_in[4];
    const float* W1 = (const float*)d_in[5];
    const float* b1 = (const float*)d_in[6];
    const float* W2 = (const float*)d_in[7];
    const float* b2 = (const float*)d_in[8];
    const float* attn_l = (const float*)d_in[9];
    const float* attn_r = (const float*)d_in[10];

    const int* src; const int* dst;
    if (n_in >= 17 && in_sizes[11] == NNODES) {  // setup_inputs dict order: type_mask at 11
        src = (const int*)d_in[15];
        dst = (const int*)d_in[16];
    } else {                                     // reference arg order: idx0..idx2 at 11..13
        src = (const int*)d_in[14];
        dst = (const int*)d_in[15];
    }
    float* out = (float*)d_out;

    const int TB = 256;
    fused_embed_scatter<<<EMBED_BLKS + SCATTER_BLKS, TB>>>(
        x0, x1, x2, W0, b0, W1, b1, W2, b2, attn_l, attn_r, src, dst);
    agg_kernel<<<(NNODES * 32 + TB - 1) / TB, TB>>>(out);
}

// round 16
// speedup vs baseline: 1.6661x; 1.2295x over previous
#include <cuda_runtime.h>
#include <cstdint>
#include <math.h>

#define NNODES   96000
#define NPERTYPE 32000
#define NEDGES   1536000
#define HD       32            // H*D
#define ROW      64            // padded row: h[32], el'[4]@32, er'[4]@36, pad; 256B-aligned
#define NEG_SLOPE 0.2f
#define LOG2E    1.4426950408889634f
#define BUCKET_CAP 64          // max in-degree capacity (Poisson(16): P(>64) ~ 1e-20)
#define ROWS_PER_BLK 128
#define EMBED_BLKS   750       // 3 types * 250
#define SCATTER_BLKS 750       // 8 edges per thread
#define XS_STRIDE 36           // 16B-aligned float4 stores; reads conflict-free

// ---------------- scratch (static device globals; no allocation) ----------------
// g_count starts zero (static init) and is RESET TO ZERO by agg_kernel at the end of
// every launch, so each launch's scatter sees zeros without an explicit zeroing pass.
__device__ float g_hx[(size_t)NNODES * ROW];         // [N,64]: h[32], el'[4], er'[4] (pre-scaled by log2e)
__device__ int   g_count[NNODES];                    // in-degree (atomic cursor)
__device__ int   g_bucket[(size_t)NNODES * BUCKET_CAP]; // src*ROW offsets grouped by dst

// ---------------- helpers ----------------
__device__ __forceinline__ void cp_async16(void* smem_ptr, const void* gptr) {
    uint32_t sa = (uint32_t)__cvta_generic_to_shared(smem_ptr);
    asm volatile("cp.async.cg.shared.global [%0], [%1], 16;" :: "r"(sa), "l"(gptr));
}
__device__ __forceinline__ void cp_commit() {
    asm volatile("cp.async.commit_group;");
}
__device__ __forceinline__ void cp_wait1() {
    asm volatile("cp.async.wait_group 1;");
}
__device__ __forceinline__ void cp_wait0() {
    asm volatile("cp.async.wait_group 0;");
}
__device__ __forceinline__ float ex2f(float x) {
    float r;
    asm("ex2.approx.ftz.f32 %0, %1;" : "=f"(r) : "f"(x));
    return r;
}
__device__ __forceinline__ float eluf(float v) {
    // v > 0 ? v : exp(v) - 1, exp via ex2
    return (v > 0.f) ? v : (ex2f(v * LOG2E) - 1.f);
}

// ---------------- embed tile: block-wide double-buffered cp.async ----------
// Block: 256 threads = 8 warps, 128 rows. Warp w: rows [16w, 16w+16).
// Thread: rgrp=lane>>2 (rows 16w+rgrp, 16w+rgrp+8), cgrp=lane&3 (8 cols == head cgrp).
template<int K>
__device__ __forceinline__ void embed_tile(
    float (* __restrict__ xs)[ROWS_PER_BLK * XS_STRIDE],
    const float* __restrict__ x,            // type-local [NPERTYPE, K]
    const float* __restrict__ W,            // [K, 32]
    const float* __restrict__ b,            // [32]
    const float* __restrict__ attn_l, const float* __restrict__ attn_r,
    int type_row_base, int grow_base)
{
    constexpr int NC = K / 32;              // chunks
    const int t = threadIdx.x;
    const int warp = t >> 5, lane = t & 31;
    const int rgrp = lane >> 2, cgrp = lane & 3;
    const int R0 = warp * 16 + rgrp;        // rows R0 and R0+8

    auto stage = [&](int buf, int k0) {
        #pragma unroll
        for (int q = 0; q < 4; q++) {
            int idx = t + 256 * q;
            int row = idx >> 3, c4 = (idx & 7) * 4;
            cp_async16(&xs[buf][row * XS_STRIDE + c4],
                       &x[(size_t)(type_row_base + row) * K + k0 + c4]);
        }
        cp_commit();
    };

    float4 bv0 = __ldg((const float4*)b + cgrp * 2);
    float4 bv1 = __ldg((const float4*)b + cgrp * 2 + 1);
    float acc[2][8];
    #pragma unroll
    for (int i = 0; i < 2; i++) {
        acc[i][0] = bv0.x; acc[i][1] = bv0.y; acc[i][2] = bv0.z; acc[i][3] = bv0.w;
        acc[i][4] = bv1.x; acc[i][5] = bv1.y; acc[i][6] = bv1.z; acc[i][7] = bv1.w;
    }

    stage(0, 0);

    #pragma unroll
    for (int c = 0; c < NC; c++) {
        if (c + 1 < NC) stage((c + 1) & 1, (c + 1) * 32);   // buffer last read in chunk c-1 (synced)
        if (c + 1 < NC) cp_wait1(); else cp_wait0();        // chunk c data arrived
        __syncthreads();

        const float* xb = xs[c & 1];
        #pragma unroll 8
        for (int kk = 0; kk < 32; kk++) {
            float4 w0 = __ldg((const float4*)(W + (size_t)(c * 32 + kk) * HD) + cgrp * 2);
            float4 w1 = __ldg((const float4*)(W + (size_t)(c * 32 + kk) * HD) + cgrp * 2 + 1);
            #pragma unroll
            for (int i = 0; i < 2; i++) {
                float xv = xb[(R0 + i * 8) * XS_STRIDE + kk];
                acc[i][0] = fmaf(xv, w0.x, acc[i][0]);
                acc[i][1] = fmaf(xv, w0.y, acc[i][1]);
                acc[i][2] = fmaf(xv, w0.z, acc[i][2]);
                acc[i][3] = fmaf(xv, w0.w, acc[i][3]);
                acc[i][4] = fmaf(xv, w1.x, acc[i][4]);
                acc[i][5] = fmaf(xv, w1.y, acc[i][5]);
                acc[i][6] = fmaf(xv, w1.z, acc[i][6]);
                acc[i][7] = fmaf(xv, w1.w, acc[i][7]);
            }
        }
        __syncthreads();
    }

    // epilogue: combined row store: h + pre-scaled el'/er' (this thread's 8 cols == head cgrp)
    float4 al0 = __ldg((const float4*)attn_l + cgrp * 2);
    float4 al1 = __ldg((const float4*)attn_l + cgrp * 2 + 1);
    float4 ar0 = __ldg((const float4*)attn_r + cgrp * 2);
    float4 ar1 = __ldg((const float4*)attn_r + cgrp * 2 + 1);
    #pragma unroll
    for (int i = 0; i < 2; i++) {
        int grow = grow_base + R0 + i * 8;
        float* rowp = g_hx + (size_t)grow * ROW;
        float4 v0 = make_float4(acc[i][0], acc[i][1], acc[i][2], acc[i][3]);
        float4 v1 = make_float4(acc[i][4], acc[i][5], acc[i][6], acc[i][7]);
        *(float4*)(rowp + cgrp * 8)     = v0;
        *(float4*)(rowp + cgrp * 8 + 4) = v1;
        float el = v0.x * al0.x + v0.y * al0.y + v0.z * al0.z + v0.w * al0.w
                 + v1.x * al1.x + v1.y * al1.y + v1.z * al1.z + v1.w * al1.w;
        float er = v0.x * ar0.x + v0.y * ar0.y + v0.z * ar0.z + v0.w * ar0.w
                 + v1.x * ar1.x + v1.y * ar1.y + v1.z * ar1.z + v1.w * ar1.w;
        rowp[32 + cgrp] = el * LOG2E;   // pre-scaled so agg uses raw EX2
        rowp[36 + cgrp] = er * LOG2E;
    }
}

// ---------------- kernel 1: FUSED embed + edge scatter ----------------
__global__ void __launch_bounds__(256) fused_embed_scatter(
    const float* __restrict__ x0, const float* __restrict__ x1, const float* __restrict__ x2,
    const float* __restrict__ W0, const float* __restrict__ b0,
    const float* __restrict__ W1, const float* __restrict__ b1,
    const float* __restrict__ W2, const float* __restrict__ b2,
    const float* __restrict__ attn_l, const float* __restrict__ attn_r,
    const int* __restrict__ src, const int* __restrict__ dst)
{
    __shared__ float xs[2][ROWS_PER_BLK * XS_STRIDE];

    if (blockIdx.x < EMBED_BLKS) {
        int type = blockIdx.x % 3;          // interleave types for load balance
        int tb   = blockIdx.x / 3;
        int type_row_base = tb * ROWS_PER_BLK;
        int grow_base = type * NPERTYPE + type_row_base;

        if (type == 0)      embed_tile<128>(xs, x0, W0, b0, attn_l, attn_r, type_row_base, grow_base);
        else if (type == 1) embed_tile<64> (xs, x1, W1, b1, attn_l, attn_r, type_row_base, grow_base);
        else                embed_tile<32> (xs, x2, W2, b2, attn_l, attn_r, type_row_base, grow_base);
    } else {
        // scatter role: 8 edges per thread (2x int4); store src*ROW (agg-ready offset)
        int sb = blockIdx.x - EMBED_BLKS;
        int base4 = (sb * 256 + threadIdx.x) * 2;        // int4 index; 2 per thread
        #pragma unroll
        for (int q = 0; q < 2; q++) {
            int i4 = base4 + q;
            if (i4 * 4 < NEDGES) {
                int4 s = __ldg((const int4*)src + i4);
                int4 d = __ldg((const int4*)dst + i4);
                int p;
                p = atomicAdd(&g_count[d.x], 1); if (p < BUCKET_CAP) g_bucket[(size_t)d.x * BUCKET_CAP + p] = s.x << 6;
                p = atomicAdd(&g_count[d.y], 1); if (p < BUCKET_CAP) g_bucket[(size_t)d.y * BUCKET_CAP + p] = s.y << 6;
                p = atomicAdd(&g_count[d.z], 1); if (p < BUCKET_CAP) g_bucket[(size_t)d.z * BUCKET_CAP + p] = s.z << 6;
                p = atomicAdd(&g_count[d.w], 1); if (p < BUCKET_CAP) g_bucket[(size_t)d.w * BUCKET_CAP + p] = s.w << 6;
            }
        }
    }
}

// ---------------- kernel 2: 4-dst-per-warp softmax aggregation + ELU ----------------
// Warp = 4 dst nodes, one per 8-lane group. Each group walks ITS OWN dst's edge list:
// per edge, lane loads float4 of h (8 lanes x 4 dims = 32 dims); e per-lane; s is
// accumulated redundantly in every lane of the group -> NO shuffles, fully parallel
// epilogue (all 32 lanes compute ELU for 4 different dst). 4-wide unrolled loop.
// Resets g_count for the next launch.
__global__ void __launch_bounds__(256) agg_kernel(float* __restrict__ out) {
    int gwarp = (blockIdx.x * blockDim.x + threadIdx.x) >> 5;
    int lane  = threadIdx.x & 31;
    int g     = lane >> 3;              // group 0..3
    int sub   = lane & 7;               // lane within group
    int node  = gwarp * 4 + g;          // this group's dst node
    if (node >= NNODES) return;

    int deg = g_count[node];
    deg = (deg > BUCKET_CAP) ? BUCKET_CAP : deg;
    const int head = sub >> 1;          // head owning this lane's 4 dims
    const int hd4  = sub * 4;
    const float er_h = g_hx[(size_t)node * ROW + 36 + head];   // pre-scaled er'
    const int* __restrict__ bkt = g_bucket + (size_t)node * BUCKET_CAP;

    float4 a = make_float4(0.f, 0.f, 0.f, 0.f);
    float s = 0.f;

    int t = 0;
    for (; t + 3 < deg; t += 4) {
        int4 off = __ldg((const int4*)(bkt + t));    // 16B-aligned (t mult of 4, base 256B)
        const float* r0 = g_hx + off.x;
        const float* r1 = g_hx + off.y;
        const float* r2 = g_hx + off.z;
        const float* r3 = g_hx + off.w;
        float  e0 = __ldg(r0 + 32 + head) + er_h;
        float  e1 = __ldg(r1 + 32 + head) + er_h;
        float  e2 = __ldg(r2 + 32 + head) + er_h;
        float  e3 = __ldg(r3 + 32 + head) + er_h;
        float4 h0 = __ldg((const float4*)(r0 + hd4));
        float4 h1 = __ldg((const float4*)(r1 + hd4));
        float4 h2 = __ldg((const float4*)(r2 + hd4));
        float4 h3 = __ldg((const float4*)(r3 + hd4));
        float x0 = ex2f(fmaxf(e0, NEG_SLOPE * e0));
        float x1 = ex2f(fmaxf(e1, NEG_SLOPE * e1));
        float x2 = ex2f(fmaxf(e2, NEG_SLOPE * e2));
        float x3 = ex2f(fmaxf(e3, NEG_SLOPE * e3));
        s += (x0 + x1) + (x2 + x3);
        a.x = fmaf(x0, h0.x, a.x);  a.y = fmaf(x0, h0.y, a.y);
        a.z = fmaf(x0, h0.z, a.z);  a.w = fmaf(x0, h0.w, a.w);
        a.x = fmaf(x1, h1.x, a.x);  a.y = fmaf(x1, h1.y, a.y);
        a.z = fmaf(x1, h1.z, a.z);  a.w = fmaf(x1, h1.w, a.w);
        a.x = fmaf(x2, h2.x, a.x);  a.y = fmaf(x2, h2.y, a.y);
        a.z = fmaf(x2, h2.z, a.z);  a.w = fmaf(x2, h2.w, a.w);
        a.x = fmaf(x3, h3.x, a.x);  a.y = fmaf(x3, h3.y, a.y);
        a.z = fmaf(x3, h3.z, a.z);  a.w = fmaf(x3, h3.w, a.w);
    }
    for (; t < deg; t++) {
        int off = __ldg(bkt + t);
        const float* r0 = g_hx + off;
        float  e0 = __ldg(r0 + 32 + head) + er_h;
        float4 h0 = __ldg((const float4*)(r0 + hd4));
        float x0 = ex2f(fmaxf(e0, NEG_SLOPE * e0));
        s += x0;
        a.x = fmaf(x0, h0.x, a.x);  a.y = fmaf(x0, h0.y, a.y);
        a.z = fmaf(x0, h0.z, a.z);  a.w = fmaf(x0, h0.w, a.w);
    }

    float inv = __fdividef(1.f, s + 1e-9f);
    float4 v;
    v.x = eluf(a.x * inv);
    v.y = eluf(a.y * inv);
    v.z = eluf(a.z * inv);
    v.w = eluf(a.w * inv);
    *(float4*)&out[(size_t)node * HD + hd4] = v;

    if (sub == 0) g_count[node] = 0;    // reset counters for next launch
}

// ---------------- launch ----------------
extern "C" void kernel_launch(void* const* d_in, const int* in_sizes, int n_in,
                              void* d_out, int out_size)
{
    const float* x0 = (const float*)d_in[0];
    const float* x1 = (const float*)d_in[1];
    const float* x2 = (const float*)d_in[2];
    const float* W0 = (const float*)d_in[3];
    const float* b0 = (const float*)d_in[4];
    const float* W1 = (const float*)d_in[5];
    const float* b1 = (const float*)d_in[6];
    const float* W2 = (const float*)d_in[7];
    const float* b2 = (const float*)d_in[8];
    const float* attn_l = (const float*)d_in[9];
    const float* attn_r = (const float*)d_in[10];

    const int* src; const int* dst;
    if (n_in >= 17 && in_sizes[11] == NNODES) {  // setup_inputs dict order: type_mask at 11
        src = (const int*)d_in[15];
        dst = (const int*)d_in[16];
    } else {                                     // reference arg order: idx0..idx2 at 11..13
        src = (const int*)d_in[14];
        dst = (const int*)d_in[15];
    }
    float* out = (float*)d_out;

    const int TB = 256;
    fused_embed_scatter<<<EMBED_BLKS + SCATTER_BLKS, TB>>>(
        x0, x1, x2, W0, b0, W1, b1, W2, b2, attn_l, attn_r, src, dst);
    // 4 dst per warp: 24000 warps = 3000 blocks of 256
    agg_kernel<<<(NNODES / 4 * 32 + TB - 1) / TB, TB>>>(out);
}